// round 12
// baseline (speedup 1.0000x reference)
#include <cuda_runtime.h>
#include <cuda_bf16.h>
#include <cstdint>
#include <cstddef>

// Problem constants
#define BB 2
#define TT 2048
#define DD 1024
#define HH 16
#define HD 64
#define D3 3072

// Scratch (allocation-free rule: __device__ globals)
__device__ __nv_bfloat16 g_qkvh[(size_t)BB * TT * D3];
__device__ __nv_bfloat16 g_qkvl[(size_t)BB * TT * D3];
__device__ __nv_bfloat16 g_xh[(size_t)BB * TT * DD];
__device__ __nv_bfloat16 g_xl[(size_t)BB * TT * DD];
__device__ __nv_bfloat16 g_wqh[(size_t)DD * D3];
__device__ __nv_bfloat16 g_wql[(size_t)DD * D3];
__device__ __nv_bfloat16 g_wph[(size_t)DD * DD];
__device__ __nv_bfloat16 g_wpl[(size_t)DD * DD];
__device__ __nv_bfloat16 g_ath[(size_t)BB * TT * DD];
__device__ __nv_bfloat16 g_atl[(size_t)BB * TT * DD];

// ---------------------------------------------------------------------------
// helpers
// ---------------------------------------------------------------------------
__device__ __forceinline__ uint32_t smem_u32(const void* p) {
    uint32_t a;
    asm("{ .reg .u64 t; cvta.to.shared.u64 t, %1; cvt.u32.u64 %0, t; }"
        : "=r"(a) : "l"(p));
    return a;
}
__device__ __forceinline__ void ldsm_x4(uint32_t* r, uint32_t addr) {
    asm volatile("ldmatrix.sync.aligned.m8n8.x4.shared.b16 {%0,%1,%2,%3}, [%4];"
                 : "=r"(r[0]), "=r"(r[1]), "=r"(r[2]), "=r"(r[3]) : "r"(addr));
}
__device__ __forceinline__ void ldsm_x4_t(uint32_t* r, uint32_t addr) {
    asm volatile("ldmatrix.sync.aligned.m8n8.x4.trans.shared.b16 {%0,%1,%2,%3}, [%4];"
                 : "=r"(r[0]), "=r"(r[1]), "=r"(r[2]), "=r"(r[3]) : "r"(addr));
}
__device__ __forceinline__ void mma_bf16(float* d, const uint32_t* a, const uint32_t* b) {
    asm volatile("mma.sync.aligned.m16n8k16.row.col.f32.bf16.bf16.f32 "
                 "{%0,%1,%2,%3}, {%4,%5,%6,%7}, {%8,%9}, {%0,%1,%2,%3};"
                 : "+f"(d[0]), "+f"(d[1]), "+f"(d[2]), "+f"(d[3])
                 : "r"(a[0]), "r"(a[1]), "r"(a[2]), "r"(a[3]),
                   "r"(b[0]), "r"(b[1]));
}
__device__ __forceinline__ void cp16(uint32_t smem_dst, const void* gsrc) {
    asm volatile("cp.async.cg.shared.global [%0], [%1], 16;"
                 :: "r"(smem_dst), "l"(gsrc));
}
__device__ __forceinline__ void cp16z(uint32_t smem_dst, const void* gsrc, bool valid) {
    const int sz = valid ? 16 : 0;
    asm volatile("cp.async.cg.shared.global [%0], [%1], 16, %2;"
                 :: "r"(smem_dst), "l"(gsrc), "r"(sz));
}
__device__ __forceinline__ void cp_commit() {
    asm volatile("cp.async.commit_group;" ::: "memory");
}
template <int N>
__device__ __forceinline__ void cp_wait() {
    asm volatile("cp.async.wait_group %0;" :: "n"(N) : "memory");
}
__device__ __forceinline__ void cvt8(const float4 v, uint2& hi, uint2& lo) {
    __nv_bfloat162 h0 = __floats2bfloat162_rn(v.x, v.y);
    __nv_bfloat162 h1 = __floats2bfloat162_rn(v.z, v.w);
    __nv_bfloat162 l0 = __floats2bfloat162_rn(v.x - __bfloat162float(h0.x),
                                              v.y - __bfloat162float(h0.y));
    __nv_bfloat162 l1 = __floats2bfloat162_rn(v.z - __bfloat162float(h1.x),
                                              v.w - __bfloat162float(h1.y));
    hi.x = *(uint32_t*)&h0; hi.y = *(uint32_t*)&h1;
    lo.x = *(uint32_t*)&l0; lo.y = *(uint32_t*)&l1;
}
__device__ __forceinline__ uint32_t pack_hi2(float a, float b) {
    __nv_bfloat162 t = __floats2bfloat162_rn(a, b);
    return *(uint32_t*)&t;
}
__device__ __forceinline__ uint32_t pack_lo2(float a, float b, uint32_t hi) {
    __nv_bfloat162 h = *(__nv_bfloat162*)&hi;
    __nv_bfloat162 t = __floats2bfloat162_rn(a - __bfloat162float(h.x),
                                             b - __bfloat162float(h.y));
    return *(uint32_t*)&t;
}

// ---------------------------------------------------------------------------
// fused fp32 -> (bf16 hi, bf16 lo) for all three inputs in ONE launch
// ---------------------------------------------------------------------------
#define N4_X  ((BB * TT * DD) / 4)
#define N4_WQ ((DD * D3) / 4)
#define N4_WP ((DD * DD) / 4)

__global__ __launch_bounds__(256)
void cvt3(const float* __restrict__ x, const float* __restrict__ wq,
          const float* __restrict__ wp,
          __nv_bfloat16* __restrict__ xh, __nv_bfloat16* __restrict__ xl,
          __nv_bfloat16* __restrict__ wqh, __nv_bfloat16* __restrict__ wql,
          __nv_bfloat16* __restrict__ wph, __nv_bfloat16* __restrict__ wpl)
{
    const int stride = gridDim.x * blockDim.x;
    const int t0 = blockIdx.x * blockDim.x + threadIdx.x;
    for (int i = t0; i < N4_X; i += stride) {
        uint2 h, l; cvt8(((const float4*)x)[i], h, l);
        ((uint2*)xh)[i] = h; ((uint2*)xl)[i] = l;
    }
    for (int i = t0; i < N4_WQ; i += stride) {
        uint2 h, l; cvt8(((const float4*)wq)[i], h, l);
        ((uint2*)wqh)[i] = h; ((uint2*)wql)[i] = l;
    }
    for (int i = t0; i < N4_WP; i += stride) {
        uint2 h, l; cvt8(((const float4*)wp)[i], h, l);
        ((uint2*)wph)[i] = h; ((uint2*)wpl)[i] = l;
    }
}

// ---------------------------------------------------------------------------
// bf16-split GEMM v6: 128x256 CTA tile, 512 threads, 16 warps (4x4) of 32x64,
// K-chunk 32, 4-stage cp.async ring. Inner loop batched into 3 MMA passes
// (AhBh, AlBh, AhBl) so accumulator RAW chains interleave across 16 accs.
// ---------------------------------------------------------------------------
#define A_STRIDE 40
#define B_STRIDE 264
#define A_BYTES  (128 * A_STRIDE * 2)
#define B_BYTES  (32 * B_STRIDE * 2)
#define OFF_AL   A_BYTES
#define OFF_BH   (2 * A_BYTES)
#define OFF_BL   (2 * A_BYTES + B_BYTES)
#define STAGE_BYTES (2 * A_BYTES + 2 * B_BYTES)   // 54272
#define NSTAGE 4
#define GEMM_SMEM (NSTAGE * STAGE_BYTES)          // 217088

__global__ __launch_bounds__(512, 1)
void gemm_bf16x3(const __nv_bfloat16* __restrict__ Ah, const __nv_bfloat16* __restrict__ Al,
                 const __nv_bfloat16* __restrict__ Bh, const __nv_bfloat16* __restrict__ Bl,
                 float* __restrict__ C,
                 __nv_bfloat16* __restrict__ Ch, __nv_bfloat16* __restrict__ Cl,
                 int M, int N, int K,
                 const float* __restrict__ bias)
{
    extern __shared__ char sm[];
    const uint32_t sb = smem_u32(sm);
    const int tid = threadIdx.x;
    const int lane = tid & 31, wid = tid >> 5;
    const int wm = wid & 3, wn = wid >> 2;          // 4 (m) x 4 (n)
    const int m0 = blockIdx.y * 128, n0 = blockIdx.x * 256;
    const int NC = K >> 5;

    const int arow = tid >> 2, aseg = tid & 3;
    const int brow = tid >> 5, bseg = tid & 31;

    const __nv_bfloat16* gAh = Ah + (size_t)(m0 + arow) * K + aseg * 8;
    const __nv_bfloat16* gAl = Al + (size_t)(m0 + arow) * K + aseg * 8;
    const __nv_bfloat16* gBh = Bh + (size_t)brow * N + n0 + bseg * 8;
    const __nv_bfloat16* gBl = Bl + (size_t)brow * N + n0 + bseg * 8;
    const uint32_t dA = arow * (A_STRIDE * 2) + aseg * 16;
    const uint32_t dB = brow * (B_STRIDE * 2) + bseg * 16;

    float acc[2][8][4];
    #pragma unroll
    for (int mt = 0; mt < 2; ++mt)
        #pragma unroll
        for (int nt = 0; nt < 8; ++nt)
            #pragma unroll
            for (int q = 0; q < 4; ++q) acc[mt][nt][q] = 0.f;

    auto issue = [&](int cc, int st) {
        const uint32_t stb = sb + (uint32_t)st * STAGE_BYTES;
        const size_t ka = (size_t)cc * 32;
        cp16(stb + dA,          gAh + ka);
        cp16(stb + OFF_AL + dA, gAl + ka);
        const size_t kb = (size_t)cc * 32 * N;
        #pragma unroll
        for (int i = 0; i < 2; ++i) {
            cp16(stb + OFF_BH + dB + i * 16 * (B_STRIDE * 2), gBh + kb + (size_t)i * 16 * N);
            cp16(stb + OFF_BL + dB + i * 16 * (B_STRIDE * 2), gBl + kb + (size_t)i * 16 * N);
        }
        cp_commit();
    };

    issue(0, 0);
    if (NC > 1) issue(1, 1);
    if (NC > 2) issue(2, 2);

    const uint32_t aRow = ((wm * 32 + (lane & 15)) * A_STRIDE + (lane >> 4) * 8) * 2;
    const int km = (lane & 7) + ((lane >> 3) & 1) * 8;
    const uint32_t bCol = OFF_BH + (km * B_STRIDE + wn * 64 + (lane >> 4) * 8) * 2;

    for (int c = 0; c < NC; ++c) {
        if (c + 2 < NC) cp_wait<2>();
        else if (c + 1 < NC) cp_wait<1>();
        else cp_wait<0>();
        __syncthreads();
        if (c + 3 < NC) issue(c + 3, (c + 3) & 3);

        const uint32_t stb = sb + (uint32_t)(c & 3) * STAGE_BYTES;
        #pragma unroll
        for (int ks = 0; ks < 2; ++ks) {
            const int k0 = ks * 16;
            uint32_t ahr[2][4], alr[2][4];
            #pragma unroll
            for (int mt = 0; mt < 2; ++mt) {
                ldsm_x4(ahr[mt], stb + aRow + (mt * 16 * A_STRIDE + k0) * 2);
                ldsm_x4(alr[mt], stb + OFF_AL + aRow + (mt * 16 * A_STRIDE + k0) * 2);
            }
            uint32_t bf[16];
            #pragma unroll
            for (int j = 0; j < 4; ++j)
                ldsm_x4_t(bf + j * 4, stb + bCol + (k0 * B_STRIDE + j * 16) * 2);
            // pass 1: Ah * Bh — 16 independent accumulators
            #pragma unroll
            for (int mt = 0; mt < 2; ++mt)
                #pragma unroll
                for (int nt = 0; nt < 8; ++nt)
                    mma_bf16(acc[mt][nt], ahr[mt], bf + nt * 2);
            // pass 2: Al * Bh
            #pragma unroll
            for (int mt = 0; mt < 2; ++mt)
                #pragma unroll
                for (int nt = 0; nt < 8; ++nt)
                    mma_bf16(acc[mt][nt], alr[mt], bf + nt * 2);
            // reload B-lo into same regs, then pass 3: Ah * Bl
            #pragma unroll
            for (int j = 0; j < 4; ++j)
                ldsm_x4_t(bf + j * 4, stb + B_BYTES + bCol + (k0 * B_STRIDE + j * 16) * 2);
            #pragma unroll
            for (int mt = 0; mt < 2; ++mt)
                #pragma unroll
                for (int nt = 0; nt < 8; ++nt)
                    mma_bf16(acc[mt][nt], ahr[mt], bf + nt * 2);
        }
    }

    const int row = m0 + wm * 32 + (lane >> 2);
    const int colb = n0 + wn * 64 + (lane & 3) * 2;
    #pragma unroll
    for (int nt = 0; nt < 8; ++nt) {
        float2 bv = make_float2(0.f, 0.f);
        if (bias) bv = *(const float2*)(bias + colb + nt * 8);
        #pragma unroll
        for (int mt = 0; mt < 2; ++mt) {
            const float* d = acc[mt][nt];
            const float v00 = d[0] + bv.x, v01 = d[1] + bv.y;
            const float v10 = d[2] + bv.x, v11 = d[3] + bv.y;
            const size_t i0 = (size_t)(row + mt * 16) * N + colb + nt * 8;
            const size_t i1 = (size_t)(row + mt * 16 + 8) * N + colb + nt * 8;
            if (Ch) {
                uint32_t h0 = pack_hi2(v00, v01), l0 = pack_lo2(v00, v01, h0);
                uint32_t h1 = pack_hi2(v10, v11), l1 = pack_lo2(v10, v11, h1);
                *(uint32_t*)&Ch[i0] = h0; *(uint32_t*)&Cl[i0] = l0;
                *(uint32_t*)&Ch[i1] = h1; *(uint32_t*)&Cl[i1] = l1;
            } else {
                *(float2*)&C[i0] = make_float2(v00, v01);
                *(float2*)&C[i1] = make_float2(v10, v11);
            }
        }
    }
}

// ---------------------------------------------------------------------------
// Tensor-core sparse attention (unchanged R9/R11 win).
// ---------------------------------------------------------------------------
#define KSTR 72
#define SQH 0
#define SQL (64 * KSTR * 2)
#define SKH (2 * 64 * KSTR * 2)
#define SKL (SKH + 224 * KSTR * 2)
#define SVH (SKL + 224 * KSTR * 2)
#define SVL (SVH + 224 * KSTR * 2)
#define SRED (SVL + 224 * KSTR * 2)
#define SO  SKH
#define ATTN_SMEM (SRED + 1024)

__global__ __launch_bounds__(256, 1)
void attn_mma(const __nv_bfloat16* __restrict__ qh_, const __nv_bfloat16* __restrict__ ql_,
              __nv_bfloat16* __restrict__ oh, __nv_bfloat16* __restrict__ ol)
{
    const int t0 = blockIdx.x * 64;
    const int h  = blockIdx.y;
    const int b  = blockIdx.z;
    const int tid = threadIdx.x;
    const int lane = tid & 31, wid = tid >> 5;
    const int mtile = wid & 3, half = wid >> 2;

    extern __shared__ char sm[];
    const uint32_t sb = smem_u32(sm);
    const size_t baseBT = (size_t)b * TT;
    const int hoff = h * HD;

    for (int idx = tid; idx < 64 * 8; idx += 256) {
        const int r = idx >> 3, c = (idx & 7) * 8;
        const size_t go = (baseBT + t0 + r) * D3 + hoff + c;
        const uint32_t off = (r * KSTR + c) * 2;
        cp16(sb + SQH + off, qh_ + go);
        cp16(sb + SQL + off, ql_ + go);
    }
    for (int idx = tid; idx < 224 * 8; idx += 256) {
        const int r = idx >> 3, c = (idx & 7) * 8;
        int t = 0; bool valid = false;
        if (r < 128)      { t = r * 16;              valid = true; }
        else if (r < 207) { t = t0 - 15 + (r - 128); valid = (t >= 0); }
        if (t < 0) t = 0;
        const size_t go = (baseBT + t) * D3 + hoff + c;
        const uint32_t off = (r * KSTR + c) * 2;
        cp16z(sb + SKH + off, qh_ + go + 1024, valid);
        cp16z(sb + SKL + off, ql_ + go + 1024, valid);
        cp16z(sb + SVH + off, qh_ + go + 2048, valid);
        cp16z(sb + SVL + off, ql_ + go + 2048, valid);
    }
    cp_commit();
    cp_wait<0>();
    __syncthreads();

    uint32_t qh[4][4], ql[4][4];
    const uint32_t aQ = sb + SQH + ((mtile * 16 + (lane & 15)) * KSTR + (lane >> 4) * 8) * 2;
    #pragma unroll
    for (int kc = 0; kc < 4; ++kc) {
        ldsm_x4(qh[kc], aQ + kc * 32);
        ldsm_x4(ql[kc], aQ + (SQL - SQH) + kc * 32);
    }

    const uint32_t bK = sb + SKH +
        ((half * 112 + (lane & 7) + ((lane >> 4) & 1) * 8) * KSTR + ((lane >> 3) & 1) * 8) * 2;

    float cf[14][4];
    #pragma unroll
    for (int j = 0; j < 14; ++j)
        #pragma unroll
        for (int e = 0; e < 4; ++e) cf[j][e] = 0.f;

    #pragma unroll
    for (int jj = 0; jj < 7; ++jj) {
        #pragma unroll
        for (int kc = 0; kc < 4; ++kc) {
            uint32_t kh4[4], kl4[4];
            const uint32_t ad = bK + (jj * 16 * KSTR + kc * 16) * 2;
            ldsm_x4(kh4, ad);
            ldsm_x4(kl4, ad + (SKL - SKH));
            mma_bf16(cf[2 * jj],     qh[kc], kh4 + 0);
            mma_bf16(cf[2 * jj],     qh[kc], kl4 + 0);
            mma_bf16(cf[2 * jj],     ql[kc], kh4 + 0);
            mma_bf16(cf[2 * jj + 1], qh[kc], kh4 + 2);
            mma_bf16(cf[2 * jj + 1], qh[kc], kl4 + 2);
            mma_bf16(cf[2 * jj + 1], ql[kc], kh4 + 2);
        }
    }
    #pragma unroll
    for (int j = 0; j < 14; ++j)
        #pragma unroll
        for (int e = 0; e < 4; ++e) cf[j][e] *= 0.125f;

    const int r0 = mtile * 16 + (lane >> 2);
    const int r1 = r0 + 8;
    float* sMax = (float*)(sm + SRED);
    float* sSum = (float*)(sm + SRED + 512);
    const int jg = (half == 0) ? 14 : 2;

    float gm0 = -1e30f, gm1 = -1e30f;
    for (int j = 0; j < jg; ++j) {
        gm0 = fmaxf(gm0, fmaxf(cf[j][0], cf[j][1]));
        gm1 = fmaxf(gm1, fmaxf(cf[j][2], cf[j][3]));
    }
    gm0 = fmaxf(gm0, __shfl_xor_sync(0xffffffffu, gm0, 1));
    gm0 = fmaxf(gm0, __shfl_xor_sync(0xffffffffu, gm0, 2));
    gm1 = fmaxf(gm1, __shfl_xor_sync(0xffffffffu, gm1, 1));
    gm1 = fmaxf(gm1, __shfl_xor_sync(0xffffffffu, gm1, 2));
    if ((lane & 3) == 0) { sMax[half * 64 + r0] = gm0; sMax[half * 64 + r1] = gm1; }
    __syncthreads();
    const float M0 = fmaxf(sMax[r0], sMax[64 + r0]);
    const float M1 = fmaxf(sMax[r1], sMax[64 + r1]);

    float gs0 = 0.f, gs1 = 0.f;
    for (int j = 0; j < jg; ++j) {
        cf[j][0] = __expf(cf[j][0] - M0); cf[j][1] = __expf(cf[j][1] - M0);
        cf[j][2] = __expf(cf[j][2] - M1); cf[j][3] = __expf(cf[j][3] - M1);
        gs0 += cf[j][0] + cf[j][1];
        gs1 += cf[j][2] + cf[j][3];
    }
    gs0 += __shfl_xor_sync(0xffffffffu, gs0, 1);
    gs0 += __shfl_xor_sync(0xffffffffu, gs0, 2);
    gs1 += __shfl_xor_sync(0xffffffffu, gs1, 1);
    gs1 += __shfl_xor_sync(0xffffffffu, gs1, 2);
    if ((lane & 3) == 0) { sSum[half * 64 + r0] = gs0; sSum[half * 64 + r1] = gs1; }

    if (half == 1) {
        float lm0 = -1e30f, lm1 = -1e30f;
        #pragma unroll
        for (int j = 2; j < 14; ++j) {
            const int c0 = (14 + j) * 8 + (lane & 3) * 2 - 128;
            const int c1 = c0 + 1;
            if ((unsigned)(c0 - r0) > 15u) cf[j][0] = -1e30f;
            if ((unsigned)(c1 - r0) > 15u) cf[j][1] = -1e30f;
            if ((unsigned)(c0 - r1) > 15u) cf[j][2] = -1e30f;
            if ((unsigned)(c1 - r1) > 15u) cf[j][3] = -1e30f;
            lm0 = fmaxf(lm0, fmaxf(cf[j][0], cf[j][1]));
            lm1 = fmaxf(lm1, fmaxf(cf[j][2], cf[j][3]));
        }
        lm0 = fmaxf(lm0, __shfl_xor_sync(0xffffffffu, lm0, 1));
        lm0 = fmaxf(lm0, __shfl_xor_sync(0xffffffffu, lm0, 2));
        lm1 = fmaxf(lm1, __shfl_xor_sync(0xffffffffu, lm1, 1));
        lm1 = fmaxf(lm1, __shfl_xor_sync(0xffffffffu, lm1, 2));
        float ls0 = 0.f, ls1 = 0.f;
        #pragma unroll
        for (int j = 2; j < 14; ++j) {
            cf[j][0] = __expf(cf[j][0] - lm0); cf[j][1] = __expf(cf[j][1] - lm0);
            cf[j][2] = __expf(cf[j][2] - lm1); cf[j][3] = __expf(cf[j][3] - lm1);
            ls0 += cf[j][0] + cf[j][1];
            ls1 += cf[j][2] + cf[j][3];
        }
        ls0 += __shfl_xor_sync(0xffffffffu, ls0, 1);
        ls0 += __shfl_xor_sync(0xffffffffu, ls0, 2);
        ls1 += __shfl_xor_sync(0xffffffffu, ls1, 1);
        ls1 += __shfl_xor_sync(0xffffffffu, ls1, 2);
        const float il0 = 1.f / ls0, il1 = 1.f / ls1;
        #pragma unroll
        for (int j = 2; j < 14; ++j) {
            cf[j][0] *= il0; cf[j][1] *= il0;
            cf[j][2] *= il1; cf[j][3] *= il1;
        }
    }
    __syncthreads();
    const float iv0 = 1.f / (sSum[r0] + sSum[64 + r0]);
    const float iv1 = 1.f / (sSum[r1] + sSum[64 + r1]);
    for (int j = 0; j < jg; ++j) {
        cf[j][0] *= iv0; cf[j][1] *= iv0;
        cf[j][2] *= iv1; cf[j][3] *= iv1;
    }

    float of[8][4];
    #pragma unroll
    for (int nt = 0; nt < 8; ++nt)
        #pragma unroll
        for (int e = 0; e < 4; ++e) of[nt][e] = 0.f;

    const int km = (lane & 7) + ((lane >> 3) & 1) * 8;
    const uint32_t bV = sb + SVH + ((half * 112 + km) * KSTR + (lane >> 4) * 8) * 2;

    #pragma unroll
    for (int kc2 = 0; kc2 < 7; ++kc2) {
        const int j0 = 2 * kc2, j1 = j0 + 1;
        uint32_t ph[4], pl[4];
        ph[0] = pack_hi2(cf[j0][0], cf[j0][1]); pl[0] = pack_lo2(cf[j0][0], cf[j0][1], ph[0]);
        ph[1] = pack_hi2(cf[j0][2], cf[j0][3]); pl[1] = pack_lo2(cf[j0][2], cf[j0][3], ph[1]);
        ph[2] = pack_hi2(cf[j1][0], cf[j1][1]); pl[2] = pack_lo2(cf[j1][0], cf[j1][1], ph[2]);
        ph[3] = pack_hi2(cf[j1][2], cf[j1][3]); pl[3] = pack_lo2(cf[j1][2], cf[j1][3], ph[3]);
        #pragma unroll
        for (int nd2 = 0; nd2 < 4; ++nd2) {
            uint32_t vh4[4], vl4[4];
            const uint32_t ad = bV + (kc2 * 16 * KSTR + nd2 * 16) * 2;
            ldsm_x4_t(vh4, ad);
            ldsm_x4_t(vl4, ad + (SVL - SVH));
            mma_bf16(of[2 * nd2],     ph, vh4 + 0);
            mma_bf16(of[2 * nd2],     ph, vl4 + 0);
            mma_bf16(of[2 * nd2],     pl, vh4 + 0);
            mma_bf16(of[2 * nd2 + 1], ph, vh4 + 2);
            mma_bf16(of[2 * nd2 + 1], ph, vl4 + 2);
            mma_bf16(of[2 * nd2 + 1], pl, vh4 + 2);
        }
    }

    float* sO = (float*)(sm + SO);
    const int rl = lane >> 2, cb = (lane & 3) * 2;
    const int base0 = ((half * 4 + mtile) * 16 + rl) * 64;
    #pragma unroll
    for (int nt = 0; nt < 8; ++nt) {
        sO[base0 + nt * 8 + cb]     = of[nt][0];
        sO[base0 + nt * 8 + cb + 1] = of[nt][1];
        sO[base0 + 8 * 64 + nt * 8 + cb]     = of[nt][2];
        sO[base0 + 8 * 64 + nt * 8 + cb + 1] = of[nt][3];
    }
    __syncthreads();

    const int qi = tid >> 2, cg = (tid & 3) * 16;
    #pragma unroll
    for (int i = 0; i < 4; ++i) {
        const int c = cg + i * 4;
        const float4 a = *(float4*)&sO[qi * 64 + c];
        const float4 bq = *(float4*)&sO[(64 + qi) * 64 + c];
        float4 o = make_float4(a.x + bq.x, a.y + bq.y, a.z + bq.z, a.w + bq.w);
        uint2 hi, lo; cvt8(o, hi, lo);
        const size_t off = (baseBT + t0 + qi) * DD + hoff + c;
        *(uint2*)&oh[off] = hi;
        *(uint2*)&ol[off] = lo;
    }
}

// ---------------------------------------------------------------------------
extern "C" void kernel_launch(void* const* d_in, const int* in_sizes, int n_in,
                              void* d_out, int out_size)
{
    const float* x      = (const float*)d_in[0];
    const float* w_qkv  = (const float*)d_in[1];
    const float* w_proj = (const float*)d_in[2];
    const float* b_proj = (const float*)d_in[3];
    float* out = (float*)d_out;

    __nv_bfloat16 *qkvh, *qkvl, *xh, *xl, *wqh, *wql, *wph, *wpl, *ath, *atl;
    cudaGetSymbolAddress((void**)&qkvh, g_qkvh);
    cudaGetSymbolAddress((void**)&qkvl, g_qkvl);
    cudaGetSymbolAddress((void**)&xh,  g_xh);
    cudaGetSymbolAddress((void**)&xl,  g_xl);
    cudaGetSymbolAddress((void**)&wqh, g_wqh);
    cudaGetSymbolAddress((void**)&wql, g_wql);
    cudaGetSymbolAddress((void**)&wph, g_wph);
    cudaGetSymbolAddress((void**)&wpl, g_wpl);
    cudaGetSymbolAddress((void**)&ath, g_ath);
    cudaGetSymbolAddress((void**)&atl, g_atl);

    const int M = BB * TT;  // 4096

    cudaFuncSetAttribute(gemm_bf16x3, cudaFuncAttributeMaxDynamicSharedMemorySize, GEMM_SMEM);
    cudaFuncSetAttribute(attn_mma, cudaFuncAttributeMaxDynamicSharedMemorySize, ATTN_SMEM);

    // 0) split all inputs/weights into bf16 hi/lo (one launch)
    cvt3<<<1184, 256>>>(x, w_qkv, w_proj, xh, xl, wqh, wql, wph, wpl);

    // 1) qkv = x @ w_qkv  (bf16 hi/lo out)
    gemm_bf16x3<<<dim3(D3 / 256, M / 128), 512, GEMM_SMEM>>>(
        xh, xl, wqh, wql, nullptr, qkvh, qkvl, M, D3, DD, nullptr);

    // 2) tensor-core sparse attention
    attn_mma<<<dim3(TT / 64, HH, BB), 256, ATTN_SMEM>>>(qkvh, qkvl, ath, atl);

    // 3) out = attn @ w_proj + b_proj (fp32 out)
    gemm_bf16x3<<<dim3(DD / 256, M / 128), 512, GEMM_SMEM>>>(
        ath, atl, wph, wpl, out, nullptr, nullptr, M, DD, DD, b_proj);
}

// round 13
// speedup vs baseline: 1.5097x; 1.5097x over previous
#include <cuda_runtime.h>
#include <cuda_bf16.h>
#include <cstdint>
#include <cstddef>

// Problem constants
#define BB 2
#define TT 2048
#define DD 1024
#define HH 16
#define HD 64
#define D3 3072

// Scratch (allocation-free rule: __device__ globals)
__device__ __nv_bfloat16 g_qkvh[(size_t)BB * TT * D3];
__device__ __nv_bfloat16 g_qkvl[(size_t)BB * TT * D3];
__device__ __nv_bfloat16 g_xh[(size_t)BB * TT * DD];
__device__ __nv_bfloat16 g_xl[(size_t)BB * TT * DD];
__device__ __nv_bfloat16 g_wqh[(size_t)DD * D3];
__device__ __nv_bfloat16 g_wql[(size_t)DD * D3];
__device__ __nv_bfloat16 g_wph[(size_t)DD * DD];
__device__ __nv_bfloat16 g_wpl[(size_t)DD * DD];
__device__ __nv_bfloat16 g_ath[(size_t)BB * TT * DD];
__device__ __nv_bfloat16 g_atl[(size_t)BB * TT * DD];

// ---------------------------------------------------------------------------
// helpers
// ---------------------------------------------------------------------------
__device__ __forceinline__ uint32_t smem_u32(const void* p) {
    uint32_t a;
    asm("{ .reg .u64 t; cvta.to.shared.u64 t, %1; cvt.u32.u64 %0, t; }"
        : "=r"(a) : "l"(p));
    return a;
}
__device__ __forceinline__ void ldsm_x4(uint32_t* r, uint32_t addr) {
    asm volatile("ldmatrix.sync.aligned.m8n8.x4.shared.b16 {%0,%1,%2,%3}, [%4];"
                 : "=r"(r[0]), "=r"(r[1]), "=r"(r[2]), "=r"(r[3]) : "r"(addr));
}
__device__ __forceinline__ void ldsm_x4_t(uint32_t* r, uint32_t addr) {
    asm volatile("ldmatrix.sync.aligned.m8n8.x4.trans.shared.b16 {%0,%1,%2,%3}, [%4];"
                 : "=r"(r[0]), "=r"(r[1]), "=r"(r[2]), "=r"(r[3]) : "r"(addr));
}
__device__ __forceinline__ void mma_bf16(float* d, const uint32_t* a, const uint32_t* b) {
    asm volatile("mma.sync.aligned.m16n8k16.row.col.f32.bf16.bf16.f32 "
                 "{%0,%1,%2,%3}, {%4,%5,%6,%7}, {%8,%9}, {%0,%1,%2,%3};"
                 : "+f"(d[0]), "+f"(d[1]), "+f"(d[2]), "+f"(d[3])
                 : "r"(a[0]), "r"(a[1]), "r"(a[2]), "r"(a[3]),
                   "r"(b[0]), "r"(b[1]));
}
__device__ __forceinline__ void cp16(uint32_t smem_dst, const void* gsrc) {
    asm volatile("cp.async.cg.shared.global [%0], [%1], 16;"
                 :: "r"(smem_dst), "l"(gsrc));
}
__device__ __forceinline__ void cp16z(uint32_t smem_dst, const void* gsrc, bool valid) {
    const int sz = valid ? 16 : 0;
    asm volatile("cp.async.cg.shared.global [%0], [%1], 16, %2;"
                 :: "r"(smem_dst), "l"(gsrc), "r"(sz));
}
__device__ __forceinline__ void cp_commit() {
    asm volatile("cp.async.commit_group;" ::: "memory");
}
template <int N>
__device__ __forceinline__ void cp_wait() {
    asm volatile("cp.async.wait_group %0;" :: "n"(N) : "memory");
}
__device__ __forceinline__ void cvt8(const float4 v, uint2& hi, uint2& lo) {
    __nv_bfloat162 h0 = __floats2bfloat162_rn(v.x, v.y);
    __nv_bfloat162 h1 = __floats2bfloat162_rn(v.z, v.w);
    __nv_bfloat162 l0 = __floats2bfloat162_rn(v.x - __bfloat162float(h0.x),
                                              v.y - __bfloat162float(h0.y));
    __nv_bfloat162 l1 = __floats2bfloat162_rn(v.z - __bfloat162float(h1.x),
                                              v.w - __bfloat162float(h1.y));
    hi.x = *(uint32_t*)&h0; hi.y = *(uint32_t*)&h1;
    lo.x = *(uint32_t*)&l0; lo.y = *(uint32_t*)&l1;
}
__device__ __forceinline__ uint32_t pack_hi2(float a, float b) {
    __nv_bfloat162 t = __floats2bfloat162_rn(a, b);
    return *(uint32_t*)&t;
}
__device__ __forceinline__ uint32_t pack_lo2(float a, float b, uint32_t hi) {
    __nv_bfloat162 h = *(__nv_bfloat162*)&hi;
    __nv_bfloat162 t = __floats2bfloat162_rn(a - __bfloat162float(h.x),
                                             b - __bfloat162float(h.y));
    return *(uint32_t*)&t;
}

// ---------------------------------------------------------------------------
// fused fp32 -> (bf16 hi, bf16 lo) for all three inputs in ONE launch
// ---------------------------------------------------------------------------
#define N4_X  ((BB * TT * DD) / 4)
#define N4_WQ ((DD * D3) / 4)
#define N4_WP ((DD * DD) / 4)

__global__ __launch_bounds__(256)
void cvt3(const float* __restrict__ x, const float* __restrict__ wq,
          const float* __restrict__ wp,
          __nv_bfloat16* __restrict__ xh, __nv_bfloat16* __restrict__ xl,
          __nv_bfloat16* __restrict__ wqh, __nv_bfloat16* __restrict__ wql,
          __nv_bfloat16* __restrict__ wph, __nv_bfloat16* __restrict__ wpl)
{
    const int stride = gridDim.x * blockDim.x;
    const int t0 = blockIdx.x * blockDim.x + threadIdx.x;
    for (int i = t0; i < N4_X; i += stride) {
        uint2 h, l; cvt8(((const float4*)x)[i], h, l);
        ((uint2*)xh)[i] = h; ((uint2*)xl)[i] = l;
    }
    for (int i = t0; i < N4_WQ; i += stride) {
        uint2 h, l; cvt8(((const float4*)wq)[i], h, l);
        ((uint2*)wqh)[i] = h; ((uint2*)wql)[i] = l;
    }
    for (int i = t0; i < N4_WP; i += stride) {
        uint2 h, l; cvt8(((const float4*)wp)[i], h, l);
        ((uint2*)wph)[i] = h; ((uint2*)wpl)[i] = l;
    }
}

// ---------------------------------------------------------------------------
// bf16-split GEMM v7: R11 structure (128x256 CTA, 512 thr, 16 warps of 32x64,
// 4-stage ring) with MMAs per j-iteration grouped 3x4 so same-accumulator
// MMAs are separated by 3 independent ones. Register footprint == R11.
// ---------------------------------------------------------------------------
#define A_STRIDE 40
#define B_STRIDE 264
#define A_BYTES  (128 * A_STRIDE * 2)
#define B_BYTES  (32 * B_STRIDE * 2)
#define OFF_AL   A_BYTES
#define OFF_BH   (2 * A_BYTES)
#define OFF_BL   (2 * A_BYTES + B_BYTES)
#define STAGE_BYTES (2 * A_BYTES + 2 * B_BYTES)   // 54272
#define NSTAGE 4
#define GEMM_SMEM (NSTAGE * STAGE_BYTES)          // 217088

__global__ __launch_bounds__(512, 1)
void gemm_bf16x3(const __nv_bfloat16* __restrict__ Ah, const __nv_bfloat16* __restrict__ Al,
                 const __nv_bfloat16* __restrict__ Bh, const __nv_bfloat16* __restrict__ Bl,
                 float* __restrict__ C,
                 __nv_bfloat16* __restrict__ Ch, __nv_bfloat16* __restrict__ Cl,
                 int M, int N, int K,
                 const float* __restrict__ bias)
{
    extern __shared__ char sm[];
    const uint32_t sb = smem_u32(sm);
    const int tid = threadIdx.x;
    const int lane = tid & 31, wid = tid >> 5;
    const int wm = wid & 3, wn = wid >> 2;          // 4 (m) x 4 (n)
    const int m0 = blockIdx.y * 128, n0 = blockIdx.x * 256;
    const int NC = K >> 5;

    const int arow = tid >> 2, aseg = tid & 3;
    const int brow = tid >> 5, bseg = tid & 31;

    const __nv_bfloat16* gAh = Ah + (size_t)(m0 + arow) * K + aseg * 8;
    const __nv_bfloat16* gAl = Al + (size_t)(m0 + arow) * K + aseg * 8;
    const __nv_bfloat16* gBh = Bh + (size_t)brow * N + n0 + bseg * 8;
    const __nv_bfloat16* gBl = Bl + (size_t)brow * N + n0 + bseg * 8;
    const uint32_t dA = arow * (A_STRIDE * 2) + aseg * 16;
    const uint32_t dB = brow * (B_STRIDE * 2) + bseg * 16;

    float acc[2][8][4];
    #pragma unroll
    for (int mt = 0; mt < 2; ++mt)
        #pragma unroll
        for (int nt = 0; nt < 8; ++nt)
            #pragma unroll
            for (int q = 0; q < 4; ++q) acc[mt][nt][q] = 0.f;

    auto issue = [&](int cc, int st) {
        const uint32_t stb = sb + (uint32_t)st * STAGE_BYTES;
        const size_t ka = (size_t)cc * 32;
        cp16(stb + dA,          gAh + ka);
        cp16(stb + OFF_AL + dA, gAl + ka);
        const size_t kb = (size_t)cc * 32 * N;
        #pragma unroll
        for (int i = 0; i < 2; ++i) {
            cp16(stb + OFF_BH + dB + i * 16 * (B_STRIDE * 2), gBh + kb + (size_t)i * 16 * N);
            cp16(stb + OFF_BL + dB + i * 16 * (B_STRIDE * 2), gBl + kb + (size_t)i * 16 * N);
        }
        cp_commit();
    };

    issue(0, 0);
    if (NC > 1) issue(1, 1);
    if (NC > 2) issue(2, 2);

    const uint32_t aRow = ((wm * 32 + (lane & 15)) * A_STRIDE + (lane >> 4) * 8) * 2;
    const int km = (lane & 7) + ((lane >> 3) & 1) * 8;
    const uint32_t bCol = OFF_BH + (km * B_STRIDE + wn * 64 + (lane >> 4) * 8) * 2;

    for (int c = 0; c < NC; ++c) {
        if (c + 2 < NC) cp_wait<2>();
        else if (c + 1 < NC) cp_wait<1>();
        else cp_wait<0>();
        __syncthreads();
        if (c + 3 < NC) issue(c + 3, (c + 3) & 3);

        const uint32_t stb = sb + (uint32_t)(c & 3) * STAGE_BYTES;
        #pragma unroll
        for (int ks = 0; ks < 2; ++ks) {
            const int k0 = ks * 16;
            uint32_t ahr[2][4], alr[2][4];
            #pragma unroll
            for (int mt = 0; mt < 2; ++mt) {
                ldsm_x4(ahr[mt], stb + aRow + (mt * 16 * A_STRIDE + k0) * 2);
                ldsm_x4(alr[mt], stb + OFF_AL + aRow + (mt * 16 * A_STRIDE + k0) * 2);
            }
            #pragma unroll
            for (int j = 0; j < 4; ++j) {
                uint32_t bh4[4], bl4[4];
                const uint32_t ad = stb + bCol + (k0 * B_STRIDE + j * 16) * 2;
                ldsm_x4_t(bh4, ad);
                ldsm_x4_t(bl4, ad + B_BYTES);
                // group 1: Ah*Bh over 4 independent accumulators
                #pragma unroll
                for (int mt = 0; mt < 2; ++mt)
                    #pragma unroll
                    for (int u = 0; u < 2; ++u)
                        mma_bf16(acc[mt][j * 2 + u], ahr[mt], bh4 + u * 2);
                // group 2: Al*Bh
                #pragma unroll
                for (int mt = 0; mt < 2; ++mt)
                    #pragma unroll
                    for (int u = 0; u < 2; ++u)
                        mma_bf16(acc[mt][j * 2 + u], alr[mt], bh4 + u * 2);
                // group 3: Ah*Bl
                #pragma unroll
                for (int mt = 0; mt < 2; ++mt)
                    #pragma unroll
                    for (int u = 0; u < 2; ++u)
                        mma_bf16(acc[mt][j * 2 + u], ahr[mt], bl4 + u * 2);
            }
        }
    }

    const int row = m0 + wm * 32 + (lane >> 2);
    const int colb = n0 + wn * 64 + (lane & 3) * 2;
    #pragma unroll
    for (int nt = 0; nt < 8; ++nt) {
        float2 bv = make_float2(0.f, 0.f);
        if (bias) bv = *(const float2*)(bias + colb + nt * 8);
        #pragma unroll
        for (int mt = 0; mt < 2; ++mt) {
            const float* d = acc[mt][nt];
            const float v00 = d[0] + bv.x, v01 = d[1] + bv.y;
            const float v10 = d[2] + bv.x, v11 = d[3] + bv.y;
            const size_t i0 = (size_t)(row + mt * 16) * N + colb + nt * 8;
            const size_t i1 = (size_t)(row + mt * 16 + 8) * N + colb + nt * 8;
            if (Ch) {
                uint32_t h0 = pack_hi2(v00, v01), l0 = pack_lo2(v00, v01, h0);
                uint32_t h1 = pack_hi2(v10, v11), l1 = pack_lo2(v10, v11, h1);
                *(uint32_t*)&Ch[i0] = h0; *(uint32_t*)&Cl[i0] = l0;
                *(uint32_t*)&Ch[i1] = h1; *(uint32_t*)&Cl[i1] = l1;
            } else {
                *(float2*)&C[i0] = make_float2(v00, v01);
                *(float2*)&C[i1] = make_float2(v10, v11);
            }
        }
    }
}

// ---------------------------------------------------------------------------
// Tensor-core sparse attention: R9/R11 version + split commit groups so the
// V load stays in flight through QK^T and softmax.
// ---------------------------------------------------------------------------
#define KSTR 72
#define SQH 0
#define SQL (64 * KSTR * 2)
#define SKH (2 * 64 * KSTR * 2)
#define SKL (SKH + 224 * KSTR * 2)
#define SVH (SKL + 224 * KSTR * 2)
#define SVL (SVH + 224 * KSTR * 2)
#define SRED (SVL + 224 * KSTR * 2)
#define SO  SKH
#define ATTN_SMEM (SRED + 1024)

__global__ __launch_bounds__(256, 1)
void attn_mma(const __nv_bfloat16* __restrict__ qh_, const __nv_bfloat16* __restrict__ ql_,
              __nv_bfloat16* __restrict__ oh, __nv_bfloat16* __restrict__ ol)
{
    const int t0 = blockIdx.x * 64;
    const int h  = blockIdx.y;
    const int b  = blockIdx.z;
    const int tid = threadIdx.x;
    const int lane = tid & 31, wid = tid >> 5;
    const int mtile = wid & 3, half = wid >> 2;

    extern __shared__ char sm[];
    const uint32_t sb = smem_u32(sm);
    const size_t baseBT = (size_t)b * TT;
    const int hoff = h * HD;

    // ---- group A: stage Q + K ----
    for (int idx = tid; idx < 64 * 8; idx += 256) {
        const int r = idx >> 3, c = (idx & 7) * 8;
        const size_t go = (baseBT + t0 + r) * D3 + hoff + c;
        const uint32_t off = (r * KSTR + c) * 2;
        cp16(sb + SQH + off, qh_ + go);
        cp16(sb + SQL + off, ql_ + go);
    }
    for (int idx = tid; idx < 224 * 8; idx += 256) {
        const int r = idx >> 3, c = (idx & 7) * 8;
        int t = 0; bool valid = false;
        if (r < 128)      { t = r * 16;              valid = true; }
        else if (r < 207) { t = t0 - 15 + (r - 128); valid = (t >= 0); }
        if (t < 0) t = 0;
        const size_t go = (baseBT + t) * D3 + hoff + c;
        const uint32_t off = (r * KSTR + c) * 2;
        cp16z(sb + SKH + off, qh_ + go + 1024, valid);
        cp16z(sb + SKL + off, ql_ + go + 1024, valid);
    }
    cp_commit();
    // ---- group B: stage V (completes during S-phase) ----
    for (int idx = tid; idx < 224 * 8; idx += 256) {
        const int r = idx >> 3, c = (idx & 7) * 8;
        int t = 0; bool valid = false;
        if (r < 128)      { t = r * 16;              valid = true; }
        else if (r < 207) { t = t0 - 15 + (r - 128); valid = (t >= 0); }
        if (t < 0) t = 0;
        const size_t go = (baseBT + t) * D3 + hoff + c;
        const uint32_t off = (r * KSTR + c) * 2;
        cp16z(sb + SVH + off, qh_ + go + 2048, valid);
        cp16z(sb + SVL + off, ql_ + go + 2048, valid);
    }
    cp_commit();
    cp_wait<1>();      // Q + K ready; V still in flight
    __syncthreads();

    uint32_t qh[4][4], ql[4][4];
    const uint32_t aQ = sb + SQH + ((mtile * 16 + (lane & 15)) * KSTR + (lane >> 4) * 8) * 2;
    #pragma unroll
    for (int kc = 0; kc < 4; ++kc) {
        ldsm_x4(qh[kc], aQ + kc * 32);
        ldsm_x4(ql[kc], aQ + (SQL - SQH) + kc * 32);
    }

    const uint32_t bK = sb + SKH +
        ((half * 112 + (lane & 7) + ((lane >> 4) & 1) * 8) * KSTR + ((lane >> 3) & 1) * 8) * 2;

    float cf[14][4];
    #pragma unroll
    for (int j = 0; j < 14; ++j)
        #pragma unroll
        for (int e = 0; e < 4; ++e) cf[j][e] = 0.f;

    #pragma unroll
    for (int jj = 0; jj < 7; ++jj) {
        #pragma unroll
        for (int kc = 0; kc < 4; ++kc) {
            uint32_t kh4[4], kl4[4];
            const uint32_t ad = bK + (jj * 16 * KSTR + kc * 16) * 2;
            ldsm_x4(kh4, ad);
            ldsm_x4(kl4, ad + (SKL - SKH));
            mma_bf16(cf[2 * jj],     qh[kc], kh4 + 0);
            mma_bf16(cf[2 * jj],     qh[kc], kl4 + 0);
            mma_bf16(cf[2 * jj],     ql[kc], kh4 + 0);
            mma_bf16(cf[2 * jj + 1], qh[kc], kh4 + 2);
            mma_bf16(cf[2 * jj + 1], qh[kc], kl4 + 2);
            mma_bf16(cf[2 * jj + 1], ql[kc], kh4 + 2);
        }
    }
    #pragma unroll
    for (int j = 0; j < 14; ++j)
        #pragma unroll
        for (int e = 0; e < 4; ++e) cf[j][e] *= 0.125f;

    const int r0 = mtile * 16 + (lane >> 2);
    const int r1 = r0 + 8;
    float* sMax = (float*)(sm + SRED);
    float* sSum = (float*)(sm + SRED + 512);
    const int jg = (half == 0) ? 14 : 2;

    float gm0 = -1e30f, gm1 = -1e30f;
    for (int j = 0; j < jg; ++j) {
        gm0 = fmaxf(gm0, fmaxf(cf[j][0], cf[j][1]));
        gm1 = fmaxf(gm1, fmaxf(cf[j][2], cf[j][3]));
    }
    gm0 = fmaxf(gm0, __shfl_xor_sync(0xffffffffu, gm0, 1));
    gm0 = fmaxf(gm0, __shfl_xor_sync(0xffffffffu, gm0, 2));
    gm1 = fmaxf(gm1, __shfl_xor_sync(0xffffffffu, gm1, 1));
    gm1 = fmaxf(gm1, __shfl_xor_sync(0xffffffffu, gm1, 2));
    if ((lane & 3) == 0) { sMax[half * 64 + r0] = gm0; sMax[half * 64 + r1] = gm1; }
    cp_wait<0>();      // V landed; next barrier makes it visible to all
    __syncthreads();
    const float M0 = fmaxf(sMax[r0], sMax[64 + r0]);
    const float M1 = fmaxf(sMax[r1], sMax[64 + r1]);

    float gs0 = 0.f, gs1 = 0.f;
    for (int j = 0; j < jg; ++j) {
        cf[j][0] = __expf(cf[j][0] - M0); cf[j][1] = __expf(cf[j][1] - M0);
        cf[j][2] = __expf(cf[j][2] - M1); cf[j][3] = __expf(cf[j][3] - M1);
        gs0 += cf[j][0] + cf[j][1];
        gs1 += cf[j][2] + cf[j][3];
    }
    gs0 += __shfl_xor_sync(0xffffffffu, gs0, 1);
    gs0 += __shfl_xor_sync(0xffffffffu, gs0, 2);
    gs1 += __shfl_xor_sync(0xffffffffu, gs1, 1);
    gs1 += __shfl_xor_sync(0xffffffffu, gs1, 2);
    if ((lane & 3) == 0) { sSum[half * 64 + r0] = gs0; sSum[half * 64 + r1] = gs1; }

    if (half == 1) {
        float lm0 = -1e30f, lm1 = -1e30f;
        #pragma unroll
        for (int j = 2; j < 14; ++j) {
            const int c0 = (14 + j) * 8 + (lane & 3) * 2 - 128;
            const int c1 = c0 + 1;
            if ((unsigned)(c0 - r0) > 15u) cf[j][0] = -1e30f;
            if ((unsigned)(c1 - r0) > 15u) cf[j][1] = -1e30f;
            if ((unsigned)(c0 - r1) > 15u) cf[j][2] = -1e30f;
            if ((unsigned)(c1 - r1) > 15u) cf[j][3] = -1e30f;
            lm0 = fmaxf(lm0, fmaxf(cf[j][0], cf[j][1]));
            lm1 = fmaxf(lm1, fmaxf(cf[j][2], cf[j][3]));
        }
        lm0 = fmaxf(lm0, __shfl_xor_sync(0xffffffffu, lm0, 1));
        lm0 = fmaxf(lm0, __shfl_xor_sync(0xffffffffu, lm0, 2));
        lm1 = fmaxf(lm1, __shfl_xor_sync(0xffffffffu, lm1, 1));
        lm1 = fmaxf(lm1, __shfl_xor_sync(0xffffffffu, lm1, 2));
        float ls0 = 0.f, ls1 = 0.f;
        #pragma unroll
        for (int j = 2; j < 14; ++j) {
            cf[j][0] = __expf(cf[j][0] - lm0); cf[j][1] = __expf(cf[j][1] - lm0);
            cf[j][2] = __expf(cf[j][2] - lm1); cf[j][3] = __expf(cf[j][3] - lm1);
            ls0 += cf[j][0] + cf[j][1];
            ls1 += cf[j][2] + cf[j][3];
        }
        ls0 += __shfl_xor_sync(0xffffffffu, ls0, 1);
        ls0 += __shfl_xor_sync(0xffffffffu, ls0, 2);
        ls1 += __shfl_xor_sync(0xffffffffu, ls1, 1);
        ls1 += __shfl_xor_sync(0xffffffffu, ls1, 2);
        const float il0 = 1.f / ls0, il1 = 1.f / ls1;
        #pragma unroll
        for (int j = 2; j < 14; ++j) {
            cf[j][0] *= il0; cf[j][1] *= il0;
            cf[j][2] *= il1; cf[j][3] *= il1;
        }
    }
    __syncthreads();
    const float iv0 = 1.f / (sSum[r0] + sSum[64 + r0]);
    const float iv1 = 1.f / (sSum[r1] + sSum[64 + r1]);
    for (int j = 0; j < jg; ++j) {
        cf[j][0] *= iv0; cf[j][1] *= iv0;
        cf[j][2] *= iv1; cf[j][3] *= iv1;
    }

    float of[8][4];
    #pragma unroll
    for (int nt = 0; nt < 8; ++nt)
        #pragma unroll
        for (int e = 0; e < 4; ++e) of[nt][e] = 0.f;

    const int km = (lane & 7) + ((lane >> 3) & 1) * 8;
    const uint32_t bV = sb + SVH + ((half * 112 + km) * KSTR + (lane >> 4) * 8) * 2;

    #pragma unroll
    for (int kc2 = 0; kc2 < 7; ++kc2) {
        const int j0 = 2 * kc2, j1 = j0 + 1;
        uint32_t ph[4], pl[4];
        ph[0] = pack_hi2(cf[j0][0], cf[j0][1]); pl[0] = pack_lo2(cf[j0][0], cf[j0][1], ph[0]);
        ph[1] = pack_hi2(cf[j0][2], cf[j0][3]); pl[1] = pack_lo2(cf[j0][2], cf[j0][3], ph[1]);
        ph[2] = pack_hi2(cf[j1][0], cf[j1][1]); pl[2] = pack_lo2(cf[j1][0], cf[j1][1], ph[2]);
        ph[3] = pack_hi2(cf[j1][2], cf[j1][3]); pl[3] = pack_lo2(cf[j1][2], cf[j1][3], ph[3]);
        #pragma unroll
        for (int nd2 = 0; nd2 < 4; ++nd2) {
            uint32_t vh4[4], vl4[4];
            const uint32_t ad = bV + (kc2 * 16 * KSTR + nd2 * 16) * 2;
            ldsm_x4_t(vh4, ad);
            ldsm_x4_t(vl4, ad + (SVL - SVH));
            mma_bf16(of[2 * nd2],     ph, vh4 + 0);
            mma_bf16(of[2 * nd2],     ph, vl4 + 0);
            mma_bf16(of[2 * nd2],     pl, vh4 + 0);
            mma_bf16(of[2 * nd2 + 1], ph, vh4 + 2);
            mma_bf16(of[2 * nd2 + 1], ph, vl4 + 2);
            mma_bf16(of[2 * nd2 + 1], pl, vh4 + 2);
        }
    }

    float* sO = (float*)(sm + SO);
    const int rl = lane >> 2, cb = (lane & 3) * 2;
    const int base0 = ((half * 4 + mtile) * 16 + rl) * 64;
    #pragma unroll
    for (int nt = 0; nt < 8; ++nt) {
        sO[base0 + nt * 8 + cb]     = of[nt][0];
        sO[base0 + nt * 8 + cb + 1] = of[nt][1];
        sO[base0 + 8 * 64 + nt * 8 + cb]     = of[nt][2];
        sO[base0 + 8 * 64 + nt * 8 + cb + 1] = of[nt][3];
    }
    __syncthreads();

    const int qi = tid >> 2, cg = (tid & 3) * 16;
    #pragma unroll
    for (int i = 0; i < 4; ++i) {
        const int c = cg + i * 4;
        const float4 a = *(float4*)&sO[qi * 64 + c];
        const float4 bq = *(float4*)&sO[(64 + qi) * 64 + c];
        float4 o = make_float4(a.x + bq.x, a.y + bq.y, a.z + bq.z, a.w + bq.w);
        uint2 hi, lo; cvt8(o, hi, lo);
        const size_t off = (baseBT + t0 + qi) * DD + hoff + c;
        *(uint2*)&oh[off] = hi;
        *(uint2*)&ol[off] = lo;
    }
}

// ---------------------------------------------------------------------------
extern "C" void kernel_launch(void* const* d_in, const int* in_sizes, int n_in,
                              void* d_out, int out_size)
{
    const float* x      = (const float*)d_in[0];
    const float* w_qkv  = (const float*)d_in[1];
    const float* w_proj = (const float*)d_in[2];
    const float* b_proj = (const float*)d_in[3];
    float* out = (float*)d_out;

    __nv_bfloat16 *qkvh, *qkvl, *xh, *xl, *wqh, *wql, *wph, *wpl, *ath, *atl;
    cudaGetSymbolAddress((void**)&qkvh, g_qkvh);
    cudaGetSymbolAddress((void**)&qkvl, g_qkvl);
    cudaGetSymbolAddress((void**)&xh,  g_xh);
    cudaGetSymbolAddress((void**)&xl,  g_xl);
    cudaGetSymbolAddress((void**)&wqh, g_wqh);
    cudaGetSymbolAddress((void**)&wql, g_wql);
    cudaGetSymbolAddress((void**)&wph, g_wph);
    cudaGetSymbolAddress((void**)&wpl, g_wpl);
    cudaGetSymbolAddress((void**)&ath, g_ath);
    cudaGetSymbolAddress((void**)&atl, g_atl);

    const int M = BB * TT;  // 4096

    cudaFuncSetAttribute(gemm_bf16x3, cudaFuncAttributeMaxDynamicSharedMemorySize, GEMM_SMEM);
    cudaFuncSetAttribute(attn_mma, cudaFuncAttributeMaxDynamicSharedMemorySize, ATTN_SMEM);

    // 0) split all inputs/weights into bf16 hi/lo (one launch)
    cvt3<<<1184, 256>>>(x, w_qkv, w_proj, xh, xl, wqh, wql, wph, wpl);

    // 1) qkv = x @ w_qkv  (bf16 hi/lo out)
    gemm_bf16x3<<<dim3(D3 / 256, M / 128), 512, GEMM_SMEM>>>(
        xh, xl, wqh, wql, nullptr, qkvh, qkvl, M, D3, DD, nullptr);

    // 2) tensor-core sparse attention
    attn_mma<<<dim3(TT / 64, HH, BB), 256, ATTN_SMEM>>>(qkvh, qkvl, ath, atl);

    // 3) out = attn @ w_proj + b_proj (fp32 out)
    gemm_bf16x3<<<dim3(DD / 256, M / 128), 512, GEMM_SMEM>>>(
        ath, atl, wph, wpl, out, nullptr, nullptr, M, DD, DD, b_proj);
}

// round 14
// speedup vs baseline: 1.9682x; 1.3037x over previous
#include <cuda_runtime.h>
#include <cuda_bf16.h>
#include <cuda_fp16.h>
#include <cstdint>
#include <cstddef>

// Problem constants
#define BB 2
#define TT 2048
#define DD 1024
#define HH 16
#define HD 64
#define D3 3072

// Scratch (allocation-free rule: __device__ globals)
__device__ __nv_bfloat16 g_qkvh[(size_t)BB * TT * D3];
__device__ __nv_bfloat16 g_qkvl[(size_t)BB * TT * D3];
__device__ __half g_xh[(size_t)BB * TT * DD];
__device__ __half g_xl[(size_t)BB * TT * DD];
__device__ __half g_wq[(size_t)DD * D3];
__device__ __half g_wp[(size_t)DD * DD];
__device__ __half g_ath[(size_t)BB * TT * DD];
__device__ __half g_atl[(size_t)BB * TT * DD];

// ---------------------------------------------------------------------------
// helpers
// ---------------------------------------------------------------------------
__device__ __forceinline__ uint32_t smem_u32(const void* p) {
    uint32_t a;
    asm("{ .reg .u64 t; cvta.to.shared.u64 t, %1; cvt.u32.u64 %0, t; }"
        : "=r"(a) : "l"(p));
    return a;
}
__device__ __forceinline__ void ldsm_x4(uint32_t* r, uint32_t addr) {
    asm volatile("ldmatrix.sync.aligned.m8n8.x4.shared.b16 {%0,%1,%2,%3}, [%4];"
                 : "=r"(r[0]), "=r"(r[1]), "=r"(r[2]), "=r"(r[3]) : "r"(addr));
}
__device__ __forceinline__ void ldsm_x4_t(uint32_t* r, uint32_t addr) {
    asm volatile("ldmatrix.sync.aligned.m8n8.x4.trans.shared.b16 {%0,%1,%2,%3}, [%4];"
                 : "=r"(r[0]), "=r"(r[1]), "=r"(r[2]), "=r"(r[3]) : "r"(addr));
}
__device__ __forceinline__ void mma_bf16(float* d, const uint32_t* a, const uint32_t* b) {
    asm volatile("mma.sync.aligned.m16n8k16.row.col.f32.bf16.bf16.f32 "
                 "{%0,%1,%2,%3}, {%4,%5,%6,%7}, {%8,%9}, {%0,%1,%2,%3};"
                 : "+f"(d[0]), "+f"(d[1]), "+f"(d[2]), "+f"(d[3])
                 : "r"(a[0]), "r"(a[1]), "r"(a[2]), "r"(a[3]),
                   "r"(b[0]), "r"(b[1]));
}
__device__ __forceinline__ void mma_f16(float* d, const uint32_t* a, const uint32_t* b) {
    asm volatile("mma.sync.aligned.m16n8k16.row.col.f32.f16.f16.f32 "
                 "{%0,%1,%2,%3}, {%4,%5,%6,%7}, {%8,%9}, {%0,%1,%2,%3};"
                 : "+f"(d[0]), "+f"(d[1]), "+f"(d[2]), "+f"(d[3])
                 : "r"(a[0]), "r"(a[1]), "r"(a[2]), "r"(a[3]),
                   "r"(b[0]), "r"(b[1]));
}
__device__ __forceinline__ void cp16(uint32_t smem_dst, const void* gsrc) {
    asm volatile("cp.async.cg.shared.global [%0], [%1], 16;"
                 :: "r"(smem_dst), "l"(gsrc));
}
__device__ __forceinline__ void cp16z(uint32_t smem_dst, const void* gsrc, bool valid) {
    const int sz = valid ? 16 : 0;
    asm volatile("cp.async.cg.shared.global [%0], [%1], 16, %2;"
                 :: "r"(smem_dst), "l"(gsrc), "r"(sz));
}
__device__ __forceinline__ void cp_commit() {
    asm volatile("cp.async.commit_group;" ::: "memory");
}
template <int N>
__device__ __forceinline__ void cp_wait() {
    asm volatile("cp.async.wait_group %0;" :: "n"(N) : "memory");
}
// bf16 hi/lo split of float4 (used for qkv + attention internals)
__device__ __forceinline__ void cvt8(const float4 v, uint2& hi, uint2& lo) {
    __nv_bfloat162 h0 = __floats2bfloat162_rn(v.x, v.y);
    __nv_bfloat162 h1 = __floats2bfloat162_rn(v.z, v.w);
    __nv_bfloat162 l0 = __floats2bfloat162_rn(v.x - __bfloat162float(h0.x),
                                              v.y - __bfloat162float(h0.y));
    __nv_bfloat162 l1 = __floats2bfloat162_rn(v.z - __bfloat162float(h1.x),
                                              v.w - __bfloat162float(h1.y));
    hi.x = *(uint32_t*)&h0; hi.y = *(uint32_t*)&h1;
    lo.x = *(uint32_t*)&l0; lo.y = *(uint32_t*)&l1;
}
// fp16 hi/lo split of float4
__device__ __forceinline__ void cvt8h(const float4 v, uint2& hi, uint2& lo) {
    __half2 h0 = __floats2half2_rn(v.x, v.y);
    __half2 h1 = __floats2half2_rn(v.z, v.w);
    __half2 l0 = __floats2half2_rn(v.x - __half2float(h0.x),
                                   v.y - __half2float(h0.y));
    __half2 l1 = __floats2half2_rn(v.z - __half2float(h1.x),
                                   v.w - __half2float(h1.y));
    hi.x = *(uint32_t*)&h0; hi.y = *(uint32_t*)&h1;
    lo.x = *(uint32_t*)&l0; lo.y = *(uint32_t*)&l1;
}
// fp16 single conversion of float4
__device__ __forceinline__ uint2 cvt4h(const float4 v) {
    __half2 h0 = __floats2half2_rn(v.x, v.y);
    __half2 h1 = __floats2half2_rn(v.z, v.w);
    uint2 r; r.x = *(uint32_t*)&h0; r.y = *(uint32_t*)&h1;
    return r;
}
__device__ __forceinline__ uint32_t pack_hi2(float a, float b) {
    __nv_bfloat162 t = __floats2bfloat162_rn(a, b);
    return *(uint32_t*)&t;
}
__device__ __forceinline__ uint32_t pack_lo2(float a, float b, uint32_t hi) {
    __nv_bfloat162 h = *(__nv_bfloat162*)&hi;
    __nv_bfloat162 t = __floats2bfloat162_rn(a - __bfloat162float(h.x),
                                             b - __bfloat162float(h.y));
    return *(uint32_t*)&t;
}
__device__ __forceinline__ uint32_t packh2(float a, float b) {
    __half2 t = __floats2half2_rn(a, b);
    return *(uint32_t*)&t;
}
__device__ __forceinline__ uint32_t packl2h(float a, float b, uint32_t hi) {
    __half2 h = *(__half2*)&hi;
    __half2 t = __floats2half2_rn(a - __half2float(h.x), b - __half2float(h.y));
    return *(uint32_t*)&t;
}

// ---------------------------------------------------------------------------
// fused conversions: x -> fp16 hi/lo; w_qkv, w_proj -> fp16 single
// ---------------------------------------------------------------------------
#define N4_X  ((BB * TT * DD) / 4)
#define N4_WQ ((DD * D3) / 4)
#define N4_WP ((DD * DD) / 4)

__global__ __launch_bounds__(256)
void cvt3(const float* __restrict__ x, const float* __restrict__ wq,
          const float* __restrict__ wp,
          __half* __restrict__ xh, __half* __restrict__ xl,
          __half* __restrict__ wqo, __half* __restrict__ wpo)
{
    const int stride = gridDim.x * blockDim.x;
    const int t0 = blockIdx.x * blockDim.x + threadIdx.x;
    for (int i = t0; i < N4_X; i += stride) {
        uint2 h, l; cvt8h(((const float4*)x)[i], h, l);
        ((uint2*)xh)[i] = h; ((uint2*)xl)[i] = l;
    }
    for (int i = t0; i < N4_WQ; i += stride)
        ((uint2*)wqo)[i] = cvt4h(((const float4*)wq)[i]);
    for (int i = t0; i < N4_WP; i += stride)
        ((uint2*)wpo)[i] = cvt4h(((const float4*)wp)[i]);
}

// ---------------------------------------------------------------------------
// fp16 2-term GEMM: C = Ah*B + Al*B, A split fp16 hi/lo, B single fp16.
// 128x256 CTA tile, 512 threads, 16 warps (4x4) of 32x64, K-chunk 32,
// 4-stage cp.async ring.
// ---------------------------------------------------------------------------
#define A_STRIDE 40
#define B_STRIDE 264
#define A_BYTES  (128 * A_STRIDE * 2)             // 10240
#define B_BYTES  (32 * B_STRIDE * 2)              // 16896
#define OFF_AL   A_BYTES
#define OFF_B    (2 * A_BYTES)
#define STAGE_BYTES (2 * A_BYTES + B_BYTES)       // 37376
#define NSTAGE 4
#define GEMM_SMEM (NSTAGE * STAGE_BYTES)          // 149504

__global__ __launch_bounds__(512, 1)
void gemm_f16x2(const __half* __restrict__ Ah, const __half* __restrict__ Al,
                const __half* __restrict__ B,
                float* __restrict__ C,
                __nv_bfloat16* __restrict__ Ch, __nv_bfloat16* __restrict__ Cl,
                int M, int N, int K,
                const float* __restrict__ bias)
{
    extern __shared__ char sm[];
    const uint32_t sb = smem_u32(sm);
    const int tid = threadIdx.x;
    const int lane = tid & 31, wid = tid >> 5;
    const int wm = wid & 3, wn = wid >> 2;          // 4 (m) x 4 (n)
    const int m0 = blockIdx.y * 128, n0 = blockIdx.x * 256;
    const int NC = K >> 5;

    const int arow = tid >> 2, aseg = tid & 3;
    const int brow = tid >> 5, bseg = tid & 31;

    const __half* gAh = Ah + (size_t)(m0 + arow) * K + aseg * 8;
    const __half* gAl = Al + (size_t)(m0 + arow) * K + aseg * 8;
    const __half* gB  = B  + (size_t)brow * N + n0 + bseg * 8;
    const uint32_t dA = arow * (A_STRIDE * 2) + aseg * 16;
    const uint32_t dB = brow * (B_STRIDE * 2) + bseg * 16;

    float acc[2][8][4];
    #pragma unroll
    for (int mt = 0; mt < 2; ++mt)
        #pragma unroll
        for (int nt = 0; nt < 8; ++nt)
            #pragma unroll
            for (int q = 0; q < 4; ++q) acc[mt][nt][q] = 0.f;

    auto issue = [&](int cc, int st) {
        const uint32_t stb = sb + (uint32_t)st * STAGE_BYTES;
        const size_t ka = (size_t)cc * 32;
        cp16(stb + dA,          gAh + ka);
        cp16(stb + OFF_AL + dA, gAl + ka);
        const size_t kb = (size_t)cc * 32 * N;
        #pragma unroll
        for (int i = 0; i < 2; ++i)
            cp16(stb + OFF_B + dB + i * 16 * (B_STRIDE * 2), gB + kb + (size_t)i * 16 * N);
        cp_commit();
    };

    issue(0, 0);
    if (NC > 1) issue(1, 1);
    if (NC > 2) issue(2, 2);

    const uint32_t aRow = ((wm * 32 + (lane & 15)) * A_STRIDE + (lane >> 4) * 8) * 2;
    const int km = (lane & 7) + ((lane >> 3) & 1) * 8;
    const uint32_t bCol = OFF_B + (km * B_STRIDE + wn * 64 + (lane >> 4) * 8) * 2;

    for (int c = 0; c < NC; ++c) {
        if (c + 2 < NC) cp_wait<2>();
        else if (c + 1 < NC) cp_wait<1>();
        else cp_wait<0>();
        __syncthreads();
        if (c + 3 < NC) issue(c + 3, (c + 3) & 3);

        const uint32_t stb = sb + (uint32_t)(c & 3) * STAGE_BYTES;
        #pragma unroll
        for (int ks = 0; ks < 2; ++ks) {
            const int k0 = ks * 16;
            uint32_t ahr[2][4], alr[2][4];
            #pragma unroll
            for (int mt = 0; mt < 2; ++mt) {
                ldsm_x4(ahr[mt], stb + aRow + (mt * 16 * A_STRIDE + k0) * 2);
                ldsm_x4(alr[mt], stb + OFF_AL + aRow + (mt * 16 * A_STRIDE + k0) * 2);
            }
            #pragma unroll
            for (int j = 0; j < 4; ++j) {
                uint32_t b4[4];
                ldsm_x4_t(b4, stb + bCol + (k0 * B_STRIDE + j * 16) * 2);
                // term 1: Ah*B (4 independent accumulators)
                #pragma unroll
                for (int mt = 0; mt < 2; ++mt)
                    #pragma unroll
                    for (int u = 0; u < 2; ++u)
                        mma_f16(acc[mt][j * 2 + u], ahr[mt], b4 + u * 2);
                // term 2: Al*B
                #pragma unroll
                for (int mt = 0; mt < 2; ++mt)
                    #pragma unroll
                    for (int u = 0; u < 2; ++u)
                        mma_f16(acc[mt][j * 2 + u], alr[mt], b4 + u * 2);
            }
        }
    }

    const int row = m0 + wm * 32 + (lane >> 2);
    const int colb = n0 + wn * 64 + (lane & 3) * 2;
    #pragma unroll
    for (int nt = 0; nt < 8; ++nt) {
        float2 bv = make_float2(0.f, 0.f);
        if (bias) bv = *(const float2*)(bias + colb + nt * 8);
        #pragma unroll
        for (int mt = 0; mt < 2; ++mt) {
            const float* d = acc[mt][nt];
            const float v00 = d[0] + bv.x, v01 = d[1] + bv.y;
            const float v10 = d[2] + bv.x, v11 = d[3] + bv.y;
            const size_t i0 = (size_t)(row + mt * 16) * N + colb + nt * 8;
            const size_t i1 = (size_t)(row + mt * 16 + 8) * N + colb + nt * 8;
            if (Ch) {
                uint32_t h0 = pack_hi2(v00, v01), l0 = pack_lo2(v00, v01, h0);
                uint32_t h1 = pack_hi2(v10, v11), l1 = pack_lo2(v10, v11, h1);
                *(uint32_t*)&Ch[i0] = h0; *(uint32_t*)&Cl[i0] = l0;
                *(uint32_t*)&Ch[i1] = h1; *(uint32_t*)&Cl[i1] = l1;
            } else {
                *(float2*)&C[i0] = make_float2(v00, v01);
                *(float2*)&C[i1] = make_float2(v10, v11);
            }
        }
    }
}

// ---------------------------------------------------------------------------
// Tensor-core sparse attention (R13 internals, bf16x3, split commit groups);
// epilogue emits fp16 hi/lo for the proj GEMM.
// ---------------------------------------------------------------------------
#define KSTR 72
#define SQH 0
#define SQL (64 * KSTR * 2)
#define SKH (2 * 64 * KSTR * 2)
#define SKL (SKH + 224 * KSTR * 2)
#define SVH (SKL + 224 * KSTR * 2)
#define SVL (SVH + 224 * KSTR * 2)
#define SRED (SVL + 224 * KSTR * 2)
#define SO  SKH
#define ATTN_SMEM (SRED + 1024)

__global__ __launch_bounds__(256, 1)
void attn_mma(const __nv_bfloat16* __restrict__ qh_, const __nv_bfloat16* __restrict__ ql_,
              __half* __restrict__ oh, __half* __restrict__ ol)
{
    const int t0 = blockIdx.x * 64;
    const int h  = blockIdx.y;
    const int b  = blockIdx.z;
    const int tid = threadIdx.x;
    const int lane = tid & 31, wid = tid >> 5;
    const int mtile = wid & 3, half = wid >> 2;

    extern __shared__ char sm[];
    const uint32_t sb = smem_u32(sm);
    const size_t baseBT = (size_t)b * TT;
    const int hoff = h * HD;

    // ---- group A: stage Q + K ----
    for (int idx = tid; idx < 64 * 8; idx += 256) {
        const int r = idx >> 3, c = (idx & 7) * 8;
        const size_t go = (baseBT + t0 + r) * D3 + hoff + c;
        const uint32_t off = (r * KSTR + c) * 2;
        cp16(sb + SQH + off, qh_ + go);
        cp16(sb + SQL + off, ql_ + go);
    }
    for (int idx = tid; idx < 224 * 8; idx += 256) {
        const int r = idx >> 3, c = (idx & 7) * 8;
        int t = 0; bool valid = false;
        if (r < 128)      { t = r * 16;              valid = true; }
        else if (r < 207) { t = t0 - 15 + (r - 128); valid = (t >= 0); }
        if (t < 0) t = 0;
        const size_t go = (baseBT + t) * D3 + hoff + c;
        const uint32_t off = (r * KSTR + c) * 2;
        cp16z(sb + SKH + off, qh_ + go + 1024, valid);
        cp16z(sb + SKL + off, ql_ + go + 1024, valid);
    }
    cp_commit();
    // ---- group B: stage V (completes during S-phase) ----
    for (int idx = tid; idx < 224 * 8; idx += 256) {
        const int r = idx >> 3, c = (idx & 7) * 8;
        int t = 0; bool valid = false;
        if (r < 128)      { t = r * 16;              valid = true; }
        else if (r < 207) { t = t0 - 15 + (r - 128); valid = (t >= 0); }
        if (t < 0) t = 0;
        const size_t go = (baseBT + t) * D3 + hoff + c;
        const uint32_t off = (r * KSTR + c) * 2;
        cp16z(sb + SVH + off, qh_ + go + 2048, valid);
        cp16z(sb + SVL + off, ql_ + go + 2048, valid);
    }
    cp_commit();
    cp_wait<1>();
    __syncthreads();

    uint32_t qh[4][4], ql[4][4];
    const uint32_t aQ = sb + SQH + ((mtile * 16 + (lane & 15)) * KSTR + (lane >> 4) * 8) * 2;
    #pragma unroll
    for (int kc = 0; kc < 4; ++kc) {
        ldsm_x4(qh[kc], aQ + kc * 32);
        ldsm_x4(ql[kc], aQ + (SQL - SQH) + kc * 32);
    }

    const uint32_t bK = sb + SKH +
        ((half * 112 + (lane & 7) + ((lane >> 4) & 1) * 8) * KSTR + ((lane >> 3) & 1) * 8) * 2;

    float cf[14][4];
    #pragma unroll
    for (int j = 0; j < 14; ++j)
        #pragma unroll
        for (int e = 0; e < 4; ++e) cf[j][e] = 0.f;

    #pragma unroll
    for (int jj = 0; jj < 7; ++jj) {
        #pragma unroll
        for (int kc = 0; kc < 4; ++kc) {
            uint32_t kh4[4], kl4[4];
            const uint32_t ad = bK + (jj * 16 * KSTR + kc * 16) * 2;
            ldsm_x4(kh4, ad);
            ldsm_x4(kl4, ad + (SKL - SKH));
            mma_bf16(cf[2 * jj],     qh[kc], kh4 + 0);
            mma_bf16(cf[2 * jj],     qh[kc], kl4 + 0);
            mma_bf16(cf[2 * jj],     ql[kc], kh4 + 0);
            mma_bf16(cf[2 * jj + 1], qh[kc], kh4 + 2);
            mma_bf16(cf[2 * jj + 1], qh[kc], kl4 + 2);
            mma_bf16(cf[2 * jj + 1], ql[kc], kh4 + 2);
        }
    }
    #pragma unroll
    for (int j = 0; j < 14; ++j)
        #pragma unroll
        for (int e = 0; e < 4; ++e) cf[j][e] *= 0.125f;

    const int r0 = mtile * 16 + (lane >> 2);
    const int r1 = r0 + 8;
    float* sMax = (float*)(sm + SRED);
    float* sSum = (float*)(sm + SRED + 512);
    const int jg = (half == 0) ? 14 : 2;

    float gm0 = -1e30f, gm1 = -1e30f;
    for (int j = 0; j < jg; ++j) {
        gm0 = fmaxf(gm0, fmaxf(cf[j][0], cf[j][1]));
        gm1 = fmaxf(gm1, fmaxf(cf[j][2], cf[j][3]));
    }
    gm0 = fmaxf(gm0, __shfl_xor_sync(0xffffffffu, gm0, 1));
    gm0 = fmaxf(gm0, __shfl_xor_sync(0xffffffffu, gm0, 2));
    gm1 = fmaxf(gm1, __shfl_xor_sync(0xffffffffu, gm1, 1));
    gm1 = fmaxf(gm1, __shfl_xor_sync(0xffffffffu, gm1, 2));
    if ((lane & 3) == 0) { sMax[half * 64 + r0] = gm0; sMax[half * 64 + r1] = gm1; }
    cp_wait<0>();
    __syncthreads();
    const float M0 = fmaxf(sMax[r0], sMax[64 + r0]);
    const float M1 = fmaxf(sMax[r1], sMax[64 + r1]);

    float gs0 = 0.f, gs1 = 0.f;
    for (int j = 0; j < jg; ++j) {
        cf[j][0] = __expf(cf[j][0] - M0); cf[j][1] = __expf(cf[j][1] - M0);
        cf[j][2] = __expf(cf[j][2] - M1); cf[j][3] = __expf(cf[j][3] - M1);
        gs0 += cf[j][0] + cf[j][1];
        gs1 += cf[j][2] + cf[j][3];
    }
    gs0 += __shfl_xor_sync(0xffffffffu, gs0, 1);
    gs0 += __shfl_xor_sync(0xffffffffu, gs0, 2);
    gs1 += __shfl_xor_sync(0xffffffffu, gs1, 1);
    gs1 += __shfl_xor_sync(0xffffffffu, gs1, 2);
    if ((lane & 3) == 0) { sSum[half * 64 + r0] = gs0; sSum[half * 64 + r1] = gs1; }

    if (half == 1) {
        float lm0 = -1e30f, lm1 = -1e30f;
        #pragma unroll
        for (int j = 2; j < 14; ++j) {
            const int c0 = (14 + j) * 8 + (lane & 3) * 2 - 128;
            const int c1 = c0 + 1;
            if ((unsigned)(c0 - r0) > 15u) cf[j][0] = -1e30f;
            if ((unsigned)(c1 - r0) > 15u) cf[j][1] = -1e30f;
            if ((unsigned)(c0 - r1) > 15u) cf[j][2] = -1e30f;
            if ((unsigned)(c1 - r1) > 15u) cf[j][3] = -1e30f;
            lm0 = fmaxf(lm0, fmaxf(cf[j][0], cf[j][1]));
            lm1 = fmaxf(lm1, fmaxf(cf[j][2], cf[j][3]));
        }
        lm0 = fmaxf(lm0, __shfl_xor_sync(0xffffffffu, lm0, 1));
        lm0 = fmaxf(lm0, __shfl_xor_sync(0xffffffffu, lm0, 2));
        lm1 = fmaxf(lm1, __shfl_xor_sync(0xffffffffu, lm1, 1));
        lm1 = fmaxf(lm1, __shfl_xor_sync(0xffffffffu, lm1, 2));
        float ls0 = 0.f, ls1 = 0.f;
        #pragma unroll
        for (int j = 2; j < 14; ++j) {
            cf[j][0] = __expf(cf[j][0] - lm0); cf[j][1] = __expf(cf[j][1] - lm0);
            cf[j][2] = __expf(cf[j][2] - lm1); cf[j][3] = __expf(cf[j][3] - lm1);
            ls0 += cf[j][0] + cf[j][1];
            ls1 += cf[j][2] + cf[j][3];
        }
        ls0 += __shfl_xor_sync(0xffffffffu, ls0, 1);
        ls0 += __shfl_xor_sync(0xffffffffu, ls0, 2);
        ls1 += __shfl_xor_sync(0xffffffffu, ls1, 1);
        ls1 += __shfl_xor_sync(0xffffffffu, ls1, 2);
        const float il0 = 1.f / ls0, il1 = 1.f / ls1;
        #pragma unroll
        for (int j = 2; j < 14; ++j) {
            cf[j][0] *= il0; cf[j][1] *= il0;
            cf[j][2] *= il1; cf[j][3] *= il1;
        }
    }
    __syncthreads();
    const float iv0 = 1.f / (sSum[r0] + sSum[64 + r0]);
    const float iv1 = 1.f / (sSum[r1] + sSum[64 + r1]);
    for (int j = 0; j < jg; ++j) {
        cf[j][0] *= iv0; cf[j][1] *= iv0;
        cf[j][2] *= iv1; cf[j][3] *= iv1;
    }

    float of[8][4];
    #pragma unroll
    for (int nt = 0; nt < 8; ++nt)
        #pragma unroll
        for (int e = 0; e < 4; ++e) of[nt][e] = 0.f;

    const int km = (lane & 7) + ((lane >> 3) & 1) * 8;
    const uint32_t bV = sb + SVH + ((half * 112 + km) * KSTR + (lane >> 4) * 8) * 2;

    #pragma unroll
    for (int kc2 = 0; kc2 < 7; ++kc2) {
        const int j0 = 2 * kc2, j1 = j0 + 1;
        uint32_t ph[4], pl[4];
        ph[0] = pack_hi2(cf[j0][0], cf[j0][1]); pl[0] = pack_lo2(cf[j0][0], cf[j0][1], ph[0]);
        ph[1] = pack_hi2(cf[j0][2], cf[j0][3]); pl[1] = pack_lo2(cf[j0][2], cf[j0][3], ph[1]);
        ph[2] = pack_hi2(cf[j1][0], cf[j1][1]); pl[2] = pack_lo2(cf[j1][0], cf[j1][1], ph[2]);
        ph[3] = pack_hi2(cf[j1][2], cf[j1][3]); pl[3] = pack_lo2(cf[j1][2], cf[j1][3], ph[3]);
        #pragma unroll
        for (int nd2 = 0; nd2 < 4; ++nd2) {
            uint32_t vh4[4], vl4[4];
            const uint32_t ad = bV + (kc2 * 16 * KSTR + nd2 * 16) * 2;
            ldsm_x4_t(vh4, ad);
            ldsm_x4_t(vl4, ad + (SVL - SVH));
            mma_bf16(of[2 * nd2],     ph, vh4 + 0);
            mma_bf16(of[2 * nd2],     ph, vl4 + 0);
            mma_bf16(of[2 * nd2],     pl, vh4 + 0);
            mma_bf16(of[2 * nd2 + 1], ph, vh4 + 2);
            mma_bf16(of[2 * nd2 + 1], ph, vl4 + 2);
            mma_bf16(of[2 * nd2 + 1], pl, vh4 + 2);
        }
    }

    float* sO = (float*)(sm + SO);
    const int rl = lane >> 2, cb = (lane & 3) * 2;
    const int base0 = ((half * 4 + mtile) * 16 + rl) * 64;
    #pragma unroll
    for (int nt = 0; nt < 8; ++nt) {
        sO[base0 + nt * 8 + cb]     = of[nt][0];
        sO[base0 + nt * 8 + cb + 1] = of[nt][1];
        sO[base0 + 8 * 64 + nt * 8 + cb]     = of[nt][2];
        sO[base0 + 8 * 64 + nt * 8 + cb + 1] = of[nt][3];
    }
    __syncthreads();

    const int qi = tid >> 2, cg = (tid & 3) * 16;
    #pragma unroll
    for (int i = 0; i < 4; ++i) {
        const int c = cg + i * 4;
        const float4 a = *(float4*)&sO[qi * 64 + c];
        const float4 bq = *(float4*)&sO[(64 + qi) * 64 + c];
        const float4 o = make_float4(a.x + bq.x, a.y + bq.y, a.z + bq.z, a.w + bq.w);
        uint2 hi, lo;
        hi.x = packh2(o.x, o.y);  lo.x = packl2h(o.x, o.y, hi.x);
        hi.y = packh2(o.z, o.w);  lo.y = packl2h(o.z, o.w, hi.y);
        const size_t off = (baseBT + t0 + qi) * DD + hoff + c;
        *(uint2*)&oh[off] = hi;
        *(uint2*)&ol[off] = lo;
    }
}

// ---------------------------------------------------------------------------
extern "C" void kernel_launch(void* const* d_in, const int* in_sizes, int n_in,
                              void* d_out, int out_size)
{
    const float* x      = (const float*)d_in[0];
    const float* w_qkv  = (const float*)d_in[1];
    const float* w_proj = (const float*)d_in[2];
    const float* b_proj = (const float*)d_in[3];
    float* out = (float*)d_out;

    __nv_bfloat16 *qkvh, *qkvl;
    __half *xh, *xl, *wq, *wp, *ath, *atl;
    cudaGetSymbolAddress((void**)&qkvh, g_qkvh);
    cudaGetSymbolAddress((void**)&qkvl, g_qkvl);
    cudaGetSymbolAddress((void**)&xh,  g_xh);
    cudaGetSymbolAddress((void**)&xl,  g_xl);
    cudaGetSymbolAddress((void**)&wq,  g_wq);
    cudaGetSymbolAddress((void**)&wp,  g_wp);
    cudaGetSymbolAddress((void**)&ath, g_ath);
    cudaGetSymbolAddress((void**)&atl, g_atl);

    const int M = BB * TT;  // 4096

    cudaFuncSetAttribute(gemm_f16x2, cudaFuncAttributeMaxDynamicSharedMemorySize, GEMM_SMEM);
    cudaFuncSetAttribute(attn_mma, cudaFuncAttributeMaxDynamicSharedMemorySize, ATTN_SMEM);

    // 0) convert inputs: x -> fp16 hi/lo, weights -> fp16
    cvt3<<<1184, 256>>>(x, w_qkv, w_proj, xh, xl, wq, wp);

    // 1) qkv = x @ w_qkv  (fp16x2 MMA; emits bf16 hi/lo for attention)
    gemm_f16x2<<<dim3(D3 / 256, M / 128), 512, GEMM_SMEM>>>(
        xh, xl, wq, nullptr, qkvh, qkvl, M, D3, DD, nullptr);

    // 2) tensor-core sparse attention (bf16x3 inside; emits fp16 hi/lo)
    attn_mma<<<dim3(TT / 64, HH, BB), 256, ATTN_SMEM>>>(qkvh, qkvl, ath, atl);

    // 3) out = attn @ w_proj + b_proj (fp16x2 MMA, fp32 out)
    gemm_f16x2<<<dim3(DD / 256, M / 128), 512, GEMM_SMEM>>>(
        ath, atl, wp, out, nullptr, nullptr, M, DD, DD, b_proj);
}

// round 15
// speedup vs baseline: 2.0058x; 1.0191x over previous
#include <cuda_runtime.h>
#include <cuda_bf16.h>
#include <cuda_fp16.h>
#include <cstdint>
#include <cstddef>

// Problem constants
#define BB 2
#define TT 2048
#define DD 1024
#define HH 16
#define HD 64
#define D3 3072

// Scratch (allocation-free rule: __device__ globals)
__device__ __half g_qkvh[(size_t)BB * TT * D3];
__device__ __half g_qkvl[(size_t)BB * TT * D3];
__device__ __half g_xh[(size_t)BB * TT * DD];
__device__ __half g_xl[(size_t)BB * TT * DD];
__device__ __half g_wq[(size_t)DD * D3];
__device__ __half g_wp[(size_t)DD * DD];
__device__ __half g_ath[(size_t)BB * TT * DD];
__device__ __half g_atl[(size_t)BB * TT * DD];

// ---------------------------------------------------------------------------
// helpers
// ---------------------------------------------------------------------------
__device__ __forceinline__ uint32_t smem_u32(const void* p) {
    uint32_t a;
    asm("{ .reg .u64 t; cvta.to.shared.u64 t, %1; cvt.u32.u64 %0, t; }"
        : "=r"(a) : "l"(p));
    return a;
}
__device__ __forceinline__ void ldsm_x4(uint32_t* r, uint32_t addr) {
    asm volatile("ldmatrix.sync.aligned.m8n8.x4.shared.b16 {%0,%1,%2,%3}, [%4];"
                 : "=r"(r[0]), "=r"(r[1]), "=r"(r[2]), "=r"(r[3]) : "r"(addr));
}
__device__ __forceinline__ void ldsm_x4_t(uint32_t* r, uint32_t addr) {
    asm volatile("ldmatrix.sync.aligned.m8n8.x4.trans.shared.b16 {%0,%1,%2,%3}, [%4];"
                 : "=r"(r[0]), "=r"(r[1]), "=r"(r[2]), "=r"(r[3]) : "r"(addr));
}
__device__ __forceinline__ void mma_f16(float* d, const uint32_t* a, const uint32_t* b) {
    asm volatile("mma.sync.aligned.m16n8k16.row.col.f32.f16.f16.f32 "
                 "{%0,%1,%2,%3}, {%4,%5,%6,%7}, {%8,%9}, {%0,%1,%2,%3};"
                 : "+f"(d[0]), "+f"(d[1]), "+f"(d[2]), "+f"(d[3])
                 : "r"(a[0]), "r"(a[1]), "r"(a[2]), "r"(a[3]),
                   "r"(b[0]), "r"(b[1]));
}
__device__ __forceinline__ void cp16(uint32_t smem_dst, const void* gsrc) {
    asm volatile("cp.async.cg.shared.global [%0], [%1], 16;"
                 :: "r"(smem_dst), "l"(gsrc));
}
__device__ __forceinline__ void cp16z(uint32_t smem_dst, const void* gsrc, bool valid) {
    const int sz = valid ? 16 : 0;
    asm volatile("cp.async.cg.shared.global [%0], [%1], 16, %2;"
                 :: "r"(smem_dst), "l"(gsrc), "r"(sz));
}
__device__ __forceinline__ void cp_commit() {
    asm volatile("cp.async.commit_group;" ::: "memory");
}
template <int N>
__device__ __forceinline__ void cp_wait() {
    asm volatile("cp.async.wait_group %0;" :: "n"(N) : "memory");
}
// fp16 hi/lo split of float4
__device__ __forceinline__ void cvt8h(const float4 v, uint2& hi, uint2& lo) {
    __half2 h0 = __floats2half2_rn(v.x, v.y);
    __half2 h1 = __floats2half2_rn(v.z, v.w);
    __half2 l0 = __floats2half2_rn(v.x - __half2float(h0.x),
                                   v.y - __half2float(h0.y));
    __half2 l1 = __floats2half2_rn(v.z - __half2float(h1.x),
                                   v.w - __half2float(h1.y));
    hi.x = *(uint32_t*)&h0; hi.y = *(uint32_t*)&h1;
    lo.x = *(uint32_t*)&l0; lo.y = *(uint32_t*)&l1;
}
__device__ __forceinline__ uint2 cvt4h(const float4 v) {
    __half2 h0 = __floats2half2_rn(v.x, v.y);
    __half2 h1 = __floats2half2_rn(v.z, v.w);
    uint2 r; r.x = *(uint32_t*)&h0; r.y = *(uint32_t*)&h1;
    return r;
}
__device__ __forceinline__ uint32_t packh2(float a, float b) {
    __half2 t = __floats2half2_rn(a, b);
    return *(uint32_t*)&t;
}
__device__ __forceinline__ uint32_t packl2h(float a, float b, uint32_t hi) {
    __half2 h = *(__half2*)&hi;
    __half2 t = __floats2half2_rn(a - __half2float(h.x), b - __half2float(h.y));
    return *(uint32_t*)&t;
}

// ---------------------------------------------------------------------------
// fused conversions: x -> fp16 hi/lo; w_qkv, w_proj -> fp16 single
// ---------------------------------------------------------------------------
#define N4_X  ((BB * TT * DD) / 4)
#define N4_WQ ((DD * D3) / 4)
#define N4_WP ((DD * DD) / 4)

__global__ __launch_bounds__(256)
void cvt3(const float* __restrict__ x, const float* __restrict__ wq,
          const float* __restrict__ wp,
          __half* __restrict__ xh, __half* __restrict__ xl,
          __half* __restrict__ wqo, __half* __restrict__ wpo)
{
    const int stride = gridDim.x * blockDim.x;
    const int t0 = blockIdx.x * blockDim.x + threadIdx.x;
    for (int i = t0; i < N4_X; i += stride) {
        uint2 h, l; cvt8h(((const float4*)x)[i], h, l);
        ((uint2*)xh)[i] = h; ((uint2*)xl)[i] = l;
    }
    for (int i = t0; i < N4_WQ; i += stride)
        ((uint2*)wqo)[i] = cvt4h(((const float4*)wq)[i]);
    for (int i = t0; i < N4_WP; i += stride)
        ((uint2*)wpo)[i] = cvt4h(((const float4*)wp)[i]);
}

// ---------------------------------------------------------------------------
// fp16 2-term GEMM: C = Ah*B + Al*B. Emits fp32 C or fp16 hi/lo (Ch/Cl).
// 128x256 CTA tile, 512 threads, 16 warps (4x4) of 32x64, 4-stage ring.
// ---------------------------------------------------------------------------
#define A_STRIDE 40
#define B_STRIDE 264
#define A_BYTES  (128 * A_STRIDE * 2)
#define B_BYTES  (32 * B_STRIDE * 2)
#define OFF_AL   A_BYTES
#define OFF_B    (2 * A_BYTES)
#define STAGE_BYTES (2 * A_BYTES + B_BYTES)
#define NSTAGE 4
#define GEMM_SMEM (NSTAGE * STAGE_BYTES)

__global__ __launch_bounds__(512, 1)
void gemm_f16x2(const __half* __restrict__ Ah, const __half* __restrict__ Al,
                const __half* __restrict__ B,
                float* __restrict__ C,
                __half* __restrict__ Ch, __half* __restrict__ Cl,
                int M, int N, int K,
                const float* __restrict__ bias)
{
    extern __shared__ char sm[];
    const uint32_t sb = smem_u32(sm);
    const int tid = threadIdx.x;
    const int lane = tid & 31, wid = tid >> 5;
    const int wm = wid & 3, wn = wid >> 2;
    const int m0 = blockIdx.y * 128, n0 = blockIdx.x * 256;
    const int NC = K >> 5;

    const int arow = tid >> 2, aseg = tid & 3;
    const int brow = tid >> 5, bseg = tid & 31;

    const __half* gAh = Ah + (size_t)(m0 + arow) * K + aseg * 8;
    const __half* gAl = Al + (size_t)(m0 + arow) * K + aseg * 8;
    const __half* gB  = B  + (size_t)brow * N + n0 + bseg * 8;
    const uint32_t dA = arow * (A_STRIDE * 2) + aseg * 16;
    const uint32_t dB = brow * (B_STRIDE * 2) + bseg * 16;

    float acc[2][8][4];
    #pragma unroll
    for (int mt = 0; mt < 2; ++mt)
        #pragma unroll
        for (int nt = 0; nt < 8; ++nt)
            #pragma unroll
            for (int q = 0; q < 4; ++q) acc[mt][nt][q] = 0.f;

    auto issue = [&](int cc, int st) {
        const uint32_t stb = sb + (uint32_t)st * STAGE_BYTES;
        const size_t ka = (size_t)cc * 32;
        cp16(stb + dA,          gAh + ka);
        cp16(stb + OFF_AL + dA, gAl + ka);
        const size_t kb = (size_t)cc * 32 * N;
        #pragma unroll
        for (int i = 0; i < 2; ++i)
            cp16(stb + OFF_B + dB + i * 16 * (B_STRIDE * 2), gB + kb + (size_t)i * 16 * N);
        cp_commit();
    };

    issue(0, 0);
    if (NC > 1) issue(1, 1);
    if (NC > 2) issue(2, 2);

    const uint32_t aRow = ((wm * 32 + (lane & 15)) * A_STRIDE + (lane >> 4) * 8) * 2;
    const int km = (lane & 7) + ((lane >> 3) & 1) * 8;
    const uint32_t bCol = OFF_B + (km * B_STRIDE + wn * 64 + (lane >> 4) * 8) * 2;

    for (int c = 0; c < NC; ++c) {
        if (c + 2 < NC) cp_wait<2>();
        else if (c + 1 < NC) cp_wait<1>();
        else cp_wait<0>();
        __syncthreads();
        if (c + 3 < NC) issue(c + 3, (c + 3) & 3);

        const uint32_t stb = sb + (uint32_t)(c & 3) * STAGE_BYTES;
        #pragma unroll
        for (int ks = 0; ks < 2; ++ks) {
            const int k0 = ks * 16;
            uint32_t ahr[2][4], alr[2][4];
            #pragma unroll
            for (int mt = 0; mt < 2; ++mt) {
                ldsm_x4(ahr[mt], stb + aRow + (mt * 16 * A_STRIDE + k0) * 2);
                ldsm_x4(alr[mt], stb + OFF_AL + aRow + (mt * 16 * A_STRIDE + k0) * 2);
            }
            #pragma unroll
            for (int j = 0; j < 4; ++j) {
                uint32_t b4[4];
                ldsm_x4_t(b4, stb + bCol + (k0 * B_STRIDE + j * 16) * 2);
                #pragma unroll
                for (int mt = 0; mt < 2; ++mt)
                    #pragma unroll
                    for (int u = 0; u < 2; ++u)
                        mma_f16(acc[mt][j * 2 + u], ahr[mt], b4 + u * 2);
                #pragma unroll
                for (int mt = 0; mt < 2; ++mt)
                    #pragma unroll
                    for (int u = 0; u < 2; ++u)
                        mma_f16(acc[mt][j * 2 + u], alr[mt], b4 + u * 2);
            }
        }
    }

    const int row = m0 + wm * 32 + (lane >> 2);
    const int colb = n0 + wn * 64 + (lane & 3) * 2;
    #pragma unroll
    for (int nt = 0; nt < 8; ++nt) {
        float2 bv = make_float2(0.f, 0.f);
        if (bias) bv = *(const float2*)(bias + colb + nt * 8);
        #pragma unroll
        for (int mt = 0; mt < 2; ++mt) {
            const float* d = acc[mt][nt];
            const float v00 = d[0] + bv.x, v01 = d[1] + bv.y;
            const float v10 = d[2] + bv.x, v11 = d[3] + bv.y;
            const size_t i0 = (size_t)(row + mt * 16) * N + colb + nt * 8;
            const size_t i1 = (size_t)(row + mt * 16 + 8) * N + colb + nt * 8;
            if (Ch) {
                uint32_t h0 = packh2(v00, v01), l0 = packl2h(v00, v01, h0);
                uint32_t h1 = packh2(v10, v11), l1 = packl2h(v10, v11, h1);
                *(uint32_t*)&Ch[i0] = h0; *(uint32_t*)&Cl[i0] = l0;
                *(uint32_t*)&Ch[i1] = h1; *(uint32_t*)&Cl[i1] = l1;
            } else {
                *(float2*)&C[i0] = make_float2(v00, v01);
                *(float2*)&C[i1] = make_float2(v10, v11);
            }
        }
    }
}

// ---------------------------------------------------------------------------
// Tensor-core sparse attention, fp16x2: Q/P split hi/lo, K/V single fp16.
// Smem halves vs R14 (no Kl/Vl) -> 2 CTAs/SM. sO reuses dead Q+K region.
// ---------------------------------------------------------------------------
#define KSTR 72
#define SQH 0
#define SQL (64 * KSTR * 2)                 // 9216
#define SKH (2 * 64 * KSTR * 2)             // 18432
#define SVH (SKH + 224 * KSTR * 2)          // 50688
#define SRED (SVH + 224 * KSTR * 2)         // 82944
#define SO  0                                // Q+K region (50688 B >= 32768 B)
#define ATTN_SMEM (SRED + 1024)             // 83968

__global__ __launch_bounds__(256, 2)
void attn_mma(const __half* __restrict__ qh_, const __half* __restrict__ ql_,
              __half* __restrict__ oh, __half* __restrict__ ol)
{
    const int t0 = blockIdx.x * 64;
    const int h  = blockIdx.y;
    const int b  = blockIdx.z;
    const int tid = threadIdx.x;
    const int lane = tid & 31, wid = tid >> 5;
    const int mtile = wid & 3, half = wid >> 2;

    extern __shared__ char sm[];
    const uint32_t sb = smem_u32(sm);
    const size_t baseBT = (size_t)b * TT;
    const int hoff = h * HD;

    // ---- group A: stage Q (hi+lo) + K (hi only) ----
    for (int idx = tid; idx < 64 * 8; idx += 256) {
        const int r = idx >> 3, c = (idx & 7) * 8;
        const size_t go = (baseBT + t0 + r) * D3 + hoff + c;
        const uint32_t off = (r * KSTR + c) * 2;
        cp16(sb + SQH + off, qh_ + go);
        cp16(sb + SQL + off, ql_ + go);
    }
    for (int idx = tid; idx < 224 * 8; idx += 256) {
        const int r = idx >> 3, c = (idx & 7) * 8;
        int t = 0; bool valid = false;
        if (r < 128)      { t = r * 16;              valid = true; }
        else if (r < 207) { t = t0 - 15 + (r - 128); valid = (t >= 0); }
        if (t < 0) t = 0;
        const size_t go = (baseBT + t) * D3 + hoff + c;
        const uint32_t off = (r * KSTR + c) * 2;
        cp16z(sb + SKH + off, qh_ + go + 1024, valid);
    }
    cp_commit();
    // ---- group B: stage V (hi only; completes during S-phase) ----
    for (int idx = tid; idx < 224 * 8; idx += 256) {
        const int r = idx >> 3, c = (idx & 7) * 8;
        int t = 0; bool valid = false;
        if (r < 128)      { t = r * 16;              valid = true; }
        else if (r < 207) { t = t0 - 15 + (r - 128); valid = (t >= 0); }
        if (t < 0) t = 0;
        const size_t go = (baseBT + t) * D3 + hoff + c;
        const uint32_t off = (r * KSTR + c) * 2;
        cp16z(sb + SVH + off, qh_ + go + 2048, valid);
    }
    cp_commit();
    cp_wait<1>();      // Q + K ready; V still in flight
    __syncthreads();

    uint32_t qh[4][4], ql[4][4];
    const uint32_t aQ = sb + SQH + ((mtile * 16 + (lane & 15)) * KSTR + (lane >> 4) * 8) * 2;
    #pragma unroll
    for (int kc = 0; kc < 4; ++kc) {
        ldsm_x4(qh[kc], aQ + kc * 32);
        ldsm_x4(ql[kc], aQ + (SQL - SQH) + kc * 32);
    }

    const uint32_t bK = sb + SKH +
        ((half * 112 + (lane & 7) + ((lane >> 4) & 1) * 8) * KSTR + ((lane >> 3) & 1) * 8) * 2;

    float cf[14][4];
    #pragma unroll
    for (int j = 0; j < 14; ++j)
        #pragma unroll
        for (int e = 0; e < 4; ++e) cf[j][e] = 0.f;

    #pragma unroll
    for (int jj = 0; jj < 7; ++jj) {
        #pragma unroll
        for (int kc = 0; kc < 4; ++kc) {
            uint32_t kh4[4];
            ldsm_x4(kh4, bK + (jj * 16 * KSTR + kc * 16) * 2);
            mma_f16(cf[2 * jj],     qh[kc], kh4 + 0);
            mma_f16(cf[2 * jj],     ql[kc], kh4 + 0);
            mma_f16(cf[2 * jj + 1], qh[kc], kh4 + 2);
            mma_f16(cf[2 * jj + 1], ql[kc], kh4 + 2);
        }
    }
    #pragma unroll
    for (int j = 0; j < 14; ++j)
        #pragma unroll
        for (int e = 0; e < 4; ++e) cf[j][e] *= 0.125f;

    const int r0 = mtile * 16 + (lane >> 2);
    const int r1 = r0 + 8;
    float* sMax = (float*)(sm + SRED);
    float* sSum = (float*)(sm + SRED + 512);
    const int jg = (half == 0) ? 14 : 2;

    float gm0 = -1e30f, gm1 = -1e30f;
    for (int j = 0; j < jg; ++j) {
        gm0 = fmaxf(gm0, fmaxf(cf[j][0], cf[j][1]));
        gm1 = fmaxf(gm1, fmaxf(cf[j][2], cf[j][3]));
    }
    gm0 = fmaxf(gm0, __shfl_xor_sync(0xffffffffu, gm0, 1));
    gm0 = fmaxf(gm0, __shfl_xor_sync(0xffffffffu, gm0, 2));
    gm1 = fmaxf(gm1, __shfl_xor_sync(0xffffffffu, gm1, 1));
    gm1 = fmaxf(gm1, __shfl_xor_sync(0xffffffffu, gm1, 2));
    if ((lane & 3) == 0) { sMax[half * 64 + r0] = gm0; sMax[half * 64 + r1] = gm1; }
    cp_wait<0>();      // V landed; next barrier publishes it
    __syncthreads();
    const float M0 = fmaxf(sMax[r0], sMax[64 + r0]);
    const float M1 = fmaxf(sMax[r1], sMax[64 + r1]);

    float gs0 = 0.f, gs1 = 0.f;
    for (int j = 0; j < jg; ++j) {
        cf[j][0] = __expf(cf[j][0] - M0); cf[j][1] = __expf(cf[j][1] - M0);
        cf[j][2] = __expf(cf[j][2] - M1); cf[j][3] = __expf(cf[j][3] - M1);
        gs0 += cf[j][0] + cf[j][1];
        gs1 += cf[j][2] + cf[j][3];
    }
    gs0 += __shfl_xor_sync(0xffffffffu, gs0, 1);
    gs0 += __shfl_xor_sync(0xffffffffu, gs0, 2);
    gs1 += __shfl_xor_sync(0xffffffffu, gs1, 1);
    gs1 += __shfl_xor_sync(0xffffffffu, gs1, 2);
    if ((lane & 3) == 0) { sSum[half * 64 + r0] = gs0; sSum[half * 64 + r1] = gs1; }

    if (half == 1) {
        float lm0 = -1e30f, lm1 = -1e30f;
        #pragma unroll
        for (int j = 2; j < 14; ++j) {
            const int c0 = (14 + j) * 8 + (lane & 3) * 2 - 128;
            const int c1 = c0 + 1;
            if ((unsigned)(c0 - r0) > 15u) cf[j][0] = -1e30f;
            if ((unsigned)(c1 - r0) > 15u) cf[j][1] = -1e30f;
            if ((unsigned)(c0 - r1) > 15u) cf[j][2] = -1e30f;
            if ((unsigned)(c1 - r1) > 15u) cf[j][3] = -1e30f;
            lm0 = fmaxf(lm0, fmaxf(cf[j][0], cf[j][1]));
            lm1 = fmaxf(lm1, fmaxf(cf[j][2], cf[j][3]));
        }
        lm0 = fmaxf(lm0, __shfl_xor_sync(0xffffffffu, lm0, 1));
        lm0 = fmaxf(lm0, __shfl_xor_sync(0xffffffffu, lm0, 2));
        lm1 = fmaxf(lm1, __shfl_xor_sync(0xffffffffu, lm1, 1));
        lm1 = fmaxf(lm1, __shfl_xor_sync(0xffffffffu, lm1, 2));
        float ls0 = 0.f, ls1 = 0.f;
        #pragma unroll
        for (int j = 2; j < 14; ++j) {
            cf[j][0] = __expf(cf[j][0] - lm0); cf[j][1] = __expf(cf[j][1] - lm0);
            cf[j][2] = __expf(cf[j][2] - lm1); cf[j][3] = __expf(cf[j][3] - lm1);
            ls0 += cf[j][0] + cf[j][1];
            ls1 += cf[j][2] + cf[j][3];
        }
        ls0 += __shfl_xor_sync(0xffffffffu, ls0, 1);
        ls0 += __shfl_xor_sync(0xffffffffu, ls0, 2);
        ls1 += __shfl_xor_sync(0xffffffffu, ls1, 1);
        ls1 += __shfl_xor_sync(0xffffffffu, ls1, 2);
        const float il0 = 1.f / ls0, il1 = 1.f / ls1;
        #pragma unroll
        for (int j = 2; j < 14; ++j) {
            cf[j][0] *= il0; cf[j][1] *= il0;
            cf[j][2] *= il1; cf[j][3] *= il1;
        }
    }
    __syncthreads();
    const float iv0 = 1.f / (sSum[r0] + sSum[64 + r0]);
    const float iv1 = 1.f / (sSum[r1] + sSum[64 + r1]);
    for (int j = 0; j < jg; ++j) {
        cf[j][0] *= iv0; cf[j][1] *= iv0;
        cf[j][2] *= iv1; cf[j][3] *= iv1;
    }

    float of[8][4];
    #pragma unroll
    for (int nt = 0; nt < 8; ++nt)
        #pragma unroll
        for (int e = 0; e < 4; ++e) of[nt][e] = 0.f;

    const int km = (lane & 7) + ((lane >> 3) & 1) * 8;
    const uint32_t bV = sb + SVH + ((half * 112 + km) * KSTR + (lane >> 4) * 8) * 2;

    #pragma unroll
    for (int kc2 = 0; kc2 < 7; ++kc2) {
        const int j0 = 2 * kc2, j1 = j0 + 1;
        uint32_t ph[4], pl[4];
        ph[0] = packh2(cf[j0][0], cf[j0][1]); pl[0] = packl2h(cf[j0][0], cf[j0][1], ph[0]);
        ph[1] = packh2(cf[j0][2], cf[j0][3]); pl[1] = packl2h(cf[j0][2], cf[j0][3], ph[1]);
        ph[2] = packh2(cf[j1][0], cf[j1][1]); pl[2] = packl2h(cf[j1][0], cf[j1][1], ph[2]);
        ph[3] = packh2(cf[j1][2], cf[j1][3]); pl[3] = packl2h(cf[j1][2], cf[j1][3], ph[3]);
        #pragma unroll
        for (int nd2 = 0; nd2 < 4; ++nd2) {
            uint32_t vh4[4];
            ldsm_x4_t(vh4, bV + (kc2 * 16 * KSTR + nd2 * 16) * 2);
            mma_f16(of[2 * nd2],     ph, vh4 + 0);
            mma_f16(of[2 * nd2],     pl, vh4 + 0);
            mma_f16(of[2 * nd2 + 1], ph, vh4 + 2);
            mma_f16(of[2 * nd2 + 1], pl, vh4 + 2);
        }
    }

    // ---- reduce halves via smem (dead Q+K region; all K reads done
    //      before the softmax barriers above) ----
    float* sO = (float*)(sm + SO);
    const int rl = lane >> 2, cb = (lane & 3) * 2;
    const int base0 = ((half * 4 + mtile) * 16 + rl) * 64;
    #pragma unroll
    for (int nt = 0; nt < 8; ++nt) {
        sO[base0 + nt * 8 + cb]     = of[nt][0];
        sO[base0 + nt * 8 + cb + 1] = of[nt][1];
        sO[base0 + 8 * 64 + nt * 8 + cb]     = of[nt][2];
        sO[base0 + 8 * 64 + nt * 8 + cb + 1] = of[nt][3];
    }
    __syncthreads();

    const int qi = tid >> 2, cg = (tid & 3) * 16;
    #pragma unroll
    for (int i = 0; i < 4; ++i) {
        const int c = cg + i * 4;
        const float4 a = *(float4*)&sO[qi * 64 + c];
        const float4 bq = *(float4*)&sO[(64 + qi) * 64 + c];
        const float4 o = make_float4(a.x + bq.x, a.y + bq.y, a.z + bq.z, a.w + bq.w);
        uint2 hi, lo;
        hi.x = packh2(o.x, o.y);  lo.x = packl2h(o.x, o.y, hi.x);
        hi.y = packh2(o.z, o.w);  lo.y = packl2h(o.z, o.w, hi.y);
        const size_t off = (baseBT + t0 + qi) * DD + hoff + c;
        *(uint2*)&oh[off] = hi;
        *(uint2*)&ol[off] = lo;
    }
}

// ---------------------------------------------------------------------------
extern "C" void kernel_launch(void* const* d_in, const int* in_sizes, int n_in,
                              void* d_out, int out_size)
{
    const float* x      = (const float*)d_in[0];
    const float* w_qkv  = (const float*)d_in[1];
    const float* w_proj = (const float*)d_in[2];
    const float* b_proj = (const float*)d_in[3];
    float* out = (float*)d_out;

    __half *qkvh, *qkvl, *xh, *xl, *wq, *wp, *ath, *atl;
    cudaGetSymbolAddress((void**)&qkvh, g_qkvh);
    cudaGetSymbolAddress((void**)&qkvl, g_qkvl);
    cudaGetSymbolAddress((void**)&xh,  g_xh);
    cudaGetSymbolAddress((void**)&xl,  g_xl);
    cudaGetSymbolAddress((void**)&wq,  g_wq);
    cudaGetSymbolAddress((void**)&wp,  g_wp);
    cudaGetSymbolAddress((void**)&ath, g_ath);
    cudaGetSymbolAddress((void**)&atl, g_atl);

    const int M = BB * TT;  // 4096

    cudaFuncSetAttribute(gemm_f16x2, cudaFuncAttributeMaxDynamicSharedMemorySize, GEMM_SMEM);
    cudaFuncSetAttribute(attn_mma, cudaFuncAttributeMaxDynamicSharedMemorySize, ATTN_SMEM);

    // 0) convert inputs: x -> fp16 hi/lo, weights -> fp16
    cvt3<<<1184, 256>>>(x, w_qkv, w_proj, xh, xl, wq, wp);

    // 1) qkv = x @ w_qkv  (fp16x2 MMA; emits fp16 hi/lo)
    gemm_f16x2<<<dim3(D3 / 256, M / 128), 512, GEMM_SMEM>>>(
        xh, xl, wq, nullptr, qkvh, qkvl, M, D3, DD, nullptr);

    // 2) tensor-core sparse attention (fp16x2; emits fp16 hi/lo)
    attn_mma<<<dim3(TT / 64, HH, BB), 256, ATTN_SMEM>>>(qkvh, qkvl, ath, atl);

    // 3) out = attn @ w_proj + b_proj (fp16x2 MMA, fp32 out)
    gemm_f16x2<<<dim3(DD / 256, M / 128), 512, GEMM_SMEM>>>(
        ath, atl, wp, out, nullptr, nullptr, M, DD, DD, b_proj);
}

// round 16
// speedup vs baseline: 2.0875x; 1.0408x over previous
#include <cuda_runtime.h>
#include <cuda_bf16.h>
#include <cuda_fp16.h>
#include <cstdint>
#include <cstddef>

// Problem constants
#define BB 2
#define TT 2048
#define DD 1024
#define HH 16
#define HD 64
#define D3 3072

// Scratch (allocation-free rule: __device__ globals)
__device__ __half g_qkvh[(size_t)BB * TT * D3];
__device__ __half g_qkvl[(size_t)BB * TT * D3];
__device__ __half g_xh[(size_t)BB * TT * DD];
__device__ __half g_xl[(size_t)BB * TT * DD];
__device__ __half g_wq[(size_t)DD * D3];
__device__ __half g_wp[(size_t)DD * DD];
__device__ __half g_ath[(size_t)BB * TT * DD];
__device__ __half g_atl[(size_t)BB * TT * DD];

// ---------------------------------------------------------------------------
// helpers
// ---------------------------------------------------------------------------
__device__ __forceinline__ uint32_t smem_u32(const void* p) {
    uint32_t a;
    asm("{ .reg .u64 t; cvta.to.shared.u64 t, %1; cvt.u32.u64 %0, t; }"
        : "=r"(a) : "l"(p));
    return a;
}
__device__ __forceinline__ void ldsm_x4(uint32_t* r, uint32_t addr) {
    asm volatile("ldmatrix.sync.aligned.m8n8.x4.shared.b16 {%0,%1,%2,%3}, [%4];"
                 : "=r"(r[0]), "=r"(r[1]), "=r"(r[2]), "=r"(r[3]) : "r"(addr));
}
__device__ __forceinline__ void ldsm_x4_t(uint32_t* r, uint32_t addr) {
    asm volatile("ldmatrix.sync.aligned.m8n8.x4.trans.shared.b16 {%0,%1,%2,%3}, [%4];"
                 : "=r"(r[0]), "=r"(r[1]), "=r"(r[2]), "=r"(r[3]) : "r"(addr));
}
__device__ __forceinline__ void mma_f16(float* d, const uint32_t* a, const uint32_t* b) {
    asm volatile("mma.sync.aligned.m16n8k16.row.col.f32.f16.f16.f32 "
                 "{%0,%1,%2,%3}, {%4,%5,%6,%7}, {%8,%9}, {%0,%1,%2,%3};"
                 : "+f"(d[0]), "+f"(d[1]), "+f"(d[2]), "+f"(d[3])
                 : "r"(a[0]), "r"(a[1]), "r"(a[2]), "r"(a[3]),
                   "r"(b[0]), "r"(b[1]));
}
__device__ __forceinline__ void cp16(uint32_t smem_dst, const void* gsrc) {
    asm volatile("cp.async.cg.shared.global [%0], [%1], 16;"
                 :: "r"(smem_dst), "l"(gsrc));
}
__device__ __forceinline__ void cp16z(uint32_t smem_dst, const void* gsrc, bool valid) {
    const int sz = valid ? 16 : 0;
    asm volatile("cp.async.cg.shared.global [%0], [%1], 16, %2;"
                 :: "r"(smem_dst), "l"(gsrc), "r"(sz));
}
__device__ __forceinline__ void cp_commit() {
    asm volatile("cp.async.commit_group;" ::: "memory");
}
template <int N>
__device__ __forceinline__ void cp_wait() {
    asm volatile("cp.async.wait_group %0;" :: "n"(N) : "memory");
}
// fp16 hi/lo split of float4
__device__ __forceinline__ void cvt8h(const float4 v, uint2& hi, uint2& lo) {
    __half2 h0 = __floats2half2_rn(v.x, v.y);
    __half2 h1 = __floats2half2_rn(v.z, v.w);
    __half2 l0 = __floats2half2_rn(v.x - __half2float(h0.x),
                                   v.y - __half2float(h0.y));
    __half2 l1 = __floats2half2_rn(v.z - __half2float(h1.x),
                                   v.w - __half2float(h1.y));
    hi.x = *(uint32_t*)&h0; hi.y = *(uint32_t*)&h1;
    lo.x = *(uint32_t*)&l0; lo.y = *(uint32_t*)&l1;
}
__device__ __forceinline__ uint2 cvt4h(const float4 v) {
    __half2 h0 = __floats2half2_rn(v.x, v.y);
    __half2 h1 = __floats2half2_rn(v.z, v.w);
    uint2 r; r.x = *(uint32_t*)&h0; r.y = *(uint32_t*)&h1;
    return r;
}
__device__ __forceinline__ uint32_t packh2(float a, float b) {
    __half2 t = __floats2half2_rn(a, b);
    return *(uint32_t*)&t;
}
__device__ __forceinline__ uint32_t packl2h(float a, float b, uint32_t hi) {
    __half2 h = *(__half2*)&hi;
    __half2 t = __floats2half2_rn(a - __half2float(h.x), b - __half2float(h.y));
    return *(uint32_t*)&t;
}

// ---------------------------------------------------------------------------
// fused conversions: x -> fp16 hi/lo; w_qkv, w_proj -> fp16 single
// ---------------------------------------------------------------------------
#define N4_X  ((BB * TT * DD) / 4)
#define N4_WQ ((DD * D3) / 4)
#define N4_WP ((DD * DD) / 4)

__global__ __launch_bounds__(256)
void cvt3(const float* __restrict__ x, const float* __restrict__ wq,
          const float* __restrict__ wp,
          __half* __restrict__ xh, __half* __restrict__ xl,
          __half* __restrict__ wqo, __half* __restrict__ wpo)
{
    const int stride = gridDim.x * blockDim.x;
    const int t0 = blockIdx.x * blockDim.x + threadIdx.x;
    for (int i = t0; i < N4_X; i += stride) {
        uint2 h, l; cvt8h(((const float4*)x)[i], h, l);
        ((uint2*)xh)[i] = h; ((uint2*)xl)[i] = l;
    }
    for (int i = t0; i < N4_WQ; i += stride)
        ((uint2*)wqo)[i] = cvt4h(((const float4*)wq)[i]);
    for (int i = t0; i < N4_WP; i += stride)
        ((uint2*)wpo)[i] = cvt4h(((const float4*)wp)[i]);
}

// ---------------------------------------------------------------------------
// fp16 GEMM with column-targeted precision: C = Ah*B (+ Al*B for output
// columns < n_split). 128x256 CTA tile, 512 threads, 16 warps of 32x64,
// 4-stage cp.async ring.
// ---------------------------------------------------------------------------
#define A_STRIDE 40
#define B_STRIDE 264
#define A_BYTES  (128 * A_STRIDE * 2)
#define B_BYTES  (32 * B_STRIDE * 2)
#define OFF_AL   A_BYTES
#define OFF_B    (2 * A_BYTES)
#define STAGE_BYTES (2 * A_BYTES + B_BYTES)
#define NSTAGE 4
#define GEMM_SMEM (NSTAGE * STAGE_BYTES)

__global__ __launch_bounds__(512, 1)
void gemm_f16x2(const __half* __restrict__ Ah, const __half* __restrict__ Al,
                const __half* __restrict__ B,
                float* __restrict__ C,
                __half* __restrict__ Ch, __half* __restrict__ Cl,
                int M, int N, int K, int n_split,
                const float* __restrict__ bias)
{
    extern __shared__ char sm[];
    const uint32_t sb = smem_u32(sm);
    const int tid = threadIdx.x;
    const int lane = tid & 31, wid = tid >> 5;
    const int wm = wid & 3, wn = wid >> 2;
    const int m0 = blockIdx.y * 128, n0 = blockIdx.x * 256;
    const int NC = K >> 5;
    const bool use_lo = (n0 < n_split);   // uniform per block

    const int arow = tid >> 2, aseg = tid & 3;
    const int brow = tid >> 5, bseg = tid & 31;

    const __half* gAh = Ah + (size_t)(m0 + arow) * K + aseg * 8;
    const __half* gAl = Al + (size_t)(m0 + arow) * K + aseg * 8;
    const __half* gB  = B  + (size_t)brow * N + n0 + bseg * 8;
    const uint32_t dA = arow * (A_STRIDE * 2) + aseg * 16;
    const uint32_t dB = brow * (B_STRIDE * 2) + bseg * 16;

    float acc[2][8][4];
    #pragma unroll
    for (int mt = 0; mt < 2; ++mt)
        #pragma unroll
        for (int nt = 0; nt < 8; ++nt)
            #pragma unroll
            for (int q = 0; q < 4; ++q) acc[mt][nt][q] = 0.f;

    auto issue = [&](int cc, int st) {
        const uint32_t stb = sb + (uint32_t)st * STAGE_BYTES;
        const size_t ka = (size_t)cc * 32;
        cp16(stb + dA, gAh + ka);
        if (use_lo) cp16(stb + OFF_AL + dA, gAl + ka);
        const size_t kb = (size_t)cc * 32 * N;
        #pragma unroll
        for (int i = 0; i < 2; ++i)
            cp16(stb + OFF_B + dB + i * 16 * (B_STRIDE * 2), gB + kb + (size_t)i * 16 * N);
        cp_commit();
    };

    issue(0, 0);
    if (NC > 1) issue(1, 1);
    if (NC > 2) issue(2, 2);

    const uint32_t aRow = ((wm * 32 + (lane & 15)) * A_STRIDE + (lane >> 4) * 8) * 2;
    const int km = (lane & 7) + ((lane >> 3) & 1) * 8;
    const uint32_t bCol = OFF_B + (km * B_STRIDE + wn * 64 + (lane >> 4) * 8) * 2;

    for (int c = 0; c < NC; ++c) {
        if (c + 2 < NC) cp_wait<2>();
        else if (c + 1 < NC) cp_wait<1>();
        else cp_wait<0>();
        __syncthreads();
        if (c + 3 < NC) issue(c + 3, (c + 3) & 3);

        const uint32_t stb = sb + (uint32_t)(c & 3) * STAGE_BYTES;
        #pragma unroll
        for (int ks = 0; ks < 2; ++ks) {
            const int k0 = ks * 16;
            uint32_t ahr[2][4], alr[2][4];
            #pragma unroll
            for (int mt = 0; mt < 2; ++mt) {
                ldsm_x4(ahr[mt], stb + aRow + (mt * 16 * A_STRIDE + k0) * 2);
                if (use_lo)
                    ldsm_x4(alr[mt], stb + OFF_AL + aRow + (mt * 16 * A_STRIDE + k0) * 2);
            }
            #pragma unroll
            for (int j = 0; j < 4; ++j) {
                uint32_t b4[4];
                ldsm_x4_t(b4, stb + bCol + (k0 * B_STRIDE + j * 16) * 2);
                #pragma unroll
                for (int mt = 0; mt < 2; ++mt)
                    #pragma unroll
                    for (int u = 0; u < 2; ++u)
                        mma_f16(acc[mt][j * 2 + u], ahr[mt], b4 + u * 2);
                if (use_lo) {
                    #pragma unroll
                    for (int mt = 0; mt < 2; ++mt)
                        #pragma unroll
                        for (int u = 0; u < 2; ++u)
                            mma_f16(acc[mt][j * 2 + u], alr[mt], b4 + u * 2);
                }
            }
        }
    }

    const int row = m0 + wm * 32 + (lane >> 2);
    const int colb = n0 + wn * 64 + (lane & 3) * 2;
    #pragma unroll
    for (int nt = 0; nt < 8; ++nt) {
        float2 bv = make_float2(0.f, 0.f);
        if (bias) bv = *(const float2*)(bias + colb + nt * 8);
        #pragma unroll
        for (int mt = 0; mt < 2; ++mt) {
            const float* d = acc[mt][nt];
            const float v00 = d[0] + bv.x, v01 = d[1] + bv.y;
            const float v10 = d[2] + bv.x, v11 = d[3] + bv.y;
            const size_t i0 = (size_t)(row + mt * 16) * N + colb + nt * 8;
            const size_t i1 = (size_t)(row + mt * 16 + 8) * N + colb + nt * 8;
            if (Ch) {
                uint32_t h0 = packh2(v00, v01), l0 = packl2h(v00, v01, h0);
                uint32_t h1 = packh2(v10, v11), l1 = packl2h(v10, v11, h1);
                *(uint32_t*)&Ch[i0] = h0; *(uint32_t*)&Cl[i0] = l0;
                *(uint32_t*)&Ch[i1] = h1; *(uint32_t*)&Cl[i1] = l1;
            } else {
                *(float2*)&C[i0] = make_float2(v00, v01);
                *(float2*)&C[i1] = make_float2(v10, v11);
            }
        }
    }
}

// ---------------------------------------------------------------------------
// Tensor-core sparse attention, fp16x2 (unchanged R15 win): Q/P hi/lo,
// K/V single fp16, 2 CTAs/SM, sO in dead Q+K region.
// ---------------------------------------------------------------------------
#define KSTR 72
#define SQH 0
#define SQL (64 * KSTR * 2)
#define SKH (2 * 64 * KSTR * 2)
#define SVH (SKH + 224 * KSTR * 2)
#define SRED (SVH + 224 * KSTR * 2)
#define SO  0
#define ATTN_SMEM (SRED + 1024)

__global__ __launch_bounds__(256, 2)
void attn_mma(const __half* __restrict__ qh_, const __half* __restrict__ ql_,
              __half* __restrict__ oh, __half* __restrict__ ol)
{
    const int t0 = blockIdx.x * 64;
    const int h  = blockIdx.y;
    const int b  = blockIdx.z;
    const int tid = threadIdx.x;
    const int lane = tid & 31, wid = tid >> 5;
    const int mtile = wid & 3, half = wid >> 2;

    extern __shared__ char sm[];
    const uint32_t sb = smem_u32(sm);
    const size_t baseBT = (size_t)b * TT;
    const int hoff = h * HD;

    for (int idx = tid; idx < 64 * 8; idx += 256) {
        const int r = idx >> 3, c = (idx & 7) * 8;
        const size_t go = (baseBT + t0 + r) * D3 + hoff + c;
        const uint32_t off = (r * KSTR + c) * 2;
        cp16(sb + SQH + off, qh_ + go);
        cp16(sb + SQL + off, ql_ + go);
    }
    for (int idx = tid; idx < 224 * 8; idx += 256) {
        const int r = idx >> 3, c = (idx & 7) * 8;
        int t = 0; bool valid = false;
        if (r < 128)      { t = r * 16;              valid = true; }
        else if (r < 207) { t = t0 - 15 + (r - 128); valid = (t >= 0); }
        if (t < 0) t = 0;
        const size_t go = (baseBT + t) * D3 + hoff + c;
        const uint32_t off = (r * KSTR + c) * 2;
        cp16z(sb + SKH + off, qh_ + go + 1024, valid);
    }
    cp_commit();
    for (int idx = tid; idx < 224 * 8; idx += 256) {
        const int r = idx >> 3, c = (idx & 7) * 8;
        int t = 0; bool valid = false;
        if (r < 128)      { t = r * 16;              valid = true; }
        else if (r < 207) { t = t0 - 15 + (r - 128); valid = (t >= 0); }
        if (t < 0) t = 0;
        const size_t go = (baseBT + t) * D3 + hoff + c;
        const uint32_t off = (r * KSTR + c) * 2;
        cp16z(sb + SVH + off, qh_ + go + 2048, valid);
    }
    cp_commit();
    cp_wait<1>();
    __syncthreads();

    uint32_t qh[4][4], ql[4][4];
    const uint32_t aQ = sb + SQH + ((mtile * 16 + (lane & 15)) * KSTR + (lane >> 4) * 8) * 2;
    #pragma unroll
    for (int kc = 0; kc < 4; ++kc) {
        ldsm_x4(qh[kc], aQ + kc * 32);
        ldsm_x4(ql[kc], aQ + (SQL - SQH) + kc * 32);
    }

    const uint32_t bK = sb + SKH +
        ((half * 112 + (lane & 7) + ((lane >> 4) & 1) * 8) * KSTR + ((lane >> 3) & 1) * 8) * 2;

    float cf[14][4];
    #pragma unroll
    for (int j = 0; j < 14; ++j)
        #pragma unroll
        for (int e = 0; e < 4; ++e) cf[j][e] = 0.f;

    #pragma unroll
    for (int jj = 0; jj < 7; ++jj) {
        #pragma unroll
        for (int kc = 0; kc < 4; ++kc) {
            uint32_t kh4[4];
            ldsm_x4(kh4, bK + (jj * 16 * KSTR + kc * 16) * 2);
            mma_f16(cf[2 * jj],     qh[kc], kh4 + 0);
            mma_f16(cf[2 * jj],     ql[kc], kh4 + 0);
            mma_f16(cf[2 * jj + 1], qh[kc], kh4 + 2);
            mma_f16(cf[2 * jj + 1], ql[kc], kh4 + 2);
        }
    }
    #pragma unroll
    for (int j = 0; j < 14; ++j)
        #pragma unroll
        for (int e = 0; e < 4; ++e) cf[j][e] *= 0.125f;

    const int r0 = mtile * 16 + (lane >> 2);
    const int r1 = r0 + 8;
    float* sMax = (float*)(sm + SRED);
    float* sSum = (float*)(sm + SRED + 512);
    const int jg = (half == 0) ? 14 : 2;

    float gm0 = -1e30f, gm1 = -1e30f;
    for (int j = 0; j < jg; ++j) {
        gm0 = fmaxf(gm0, fmaxf(cf[j][0], cf[j][1]));
        gm1 = fmaxf(gm1, fmaxf(cf[j][2], cf[j][3]));
    }
    gm0 = fmaxf(gm0, __shfl_xor_sync(0xffffffffu, gm0, 1));
    gm0 = fmaxf(gm0, __shfl_xor_sync(0xffffffffu, gm0, 2));
    gm1 = fmaxf(gm1, __shfl_xor_sync(0xffffffffu, gm1, 1));
    gm1 = fmaxf(gm1, __shfl_xor_sync(0xffffffffu, gm1, 2));
    if ((lane & 3) == 0) { sMax[half * 64 + r0] = gm0; sMax[half * 64 + r1] = gm1; }
    cp_wait<0>();
    __syncthreads();
    const float M0 = fmaxf(sMax[r0], sMax[64 + r0]);
    const float M1 = fmaxf(sMax[r1], sMax[64 + r1]);

    float gs0 = 0.f, gs1 = 0.f;
    for (int j = 0; j < jg; ++j) {
        cf[j][0] = __expf(cf[j][0] - M0); cf[j][1] = __expf(cf[j][1] - M0);
        cf[j][2] = __expf(cf[j][2] - M1); cf[j][3] = __expf(cf[j][3] - M1);
        gs0 += cf[j][0] + cf[j][1];
        gs1 += cf[j][2] + cf[j][3];
    }
    gs0 += __shfl_xor_sync(0xffffffffu, gs0, 1);
    gs0 += __shfl_xor_sync(0xffffffffu, gs0, 2);
    gs1 += __shfl_xor_sync(0xffffffffu, gs1, 1);
    gs1 += __shfl_xor_sync(0xffffffffu, gs1, 2);
    if ((lane & 3) == 0) { sSum[half * 64 + r0] = gs0; sSum[half * 64 + r1] = gs1; }

    if (half == 1) {
        float lm0 = -1e30f, lm1 = -1e30f;
        #pragma unroll
        for (int j = 2; j < 14; ++j) {
            const int c0 = (14 + j) * 8 + (lane & 3) * 2 - 128;
            const int c1 = c0 + 1;
            if ((unsigned)(c0 - r0) > 15u) cf[j][0] = -1e30f;
            if ((unsigned)(c1 - r0) > 15u) cf[j][1] = -1e30f;
            if ((unsigned)(c0 - r1) > 15u) cf[j][2] = -1e30f;
            if ((unsigned)(c1 - r1) > 15u) cf[j][3] = -1e30f;
            lm0 = fmaxf(lm0, fmaxf(cf[j][0], cf[j][1]));
            lm1 = fmaxf(lm1, fmaxf(cf[j][2], cf[j][3]));
        }
        lm0 = fmaxf(lm0, __shfl_xor_sync(0xffffffffu, lm0, 1));
        lm0 = fmaxf(lm0, __shfl_xor_sync(0xffffffffu, lm0, 2));
        lm1 = fmaxf(lm1, __shfl_xor_sync(0xffffffffu, lm1, 1));
        lm1 = fmaxf(lm1, __shfl_xor_sync(0xffffffffu, lm1, 2));
        float ls0 = 0.f, ls1 = 0.f;
        #pragma unroll
        for (int j = 2; j < 14; ++j) {
            cf[j][0] = __expf(cf[j][0] - lm0); cf[j][1] = __expf(cf[j][1] - lm0);
            cf[j][2] = __expf(cf[j][2] - lm1); cf[j][3] = __expf(cf[j][3] - lm1);
            ls0 += cf[j][0] + cf[j][1];
            ls1 += cf[j][2] + cf[j][3];
        }
        ls0 += __shfl_xor_sync(0xffffffffu, ls0, 1);
        ls0 += __shfl_xor_sync(0xffffffffu, ls0, 2);
        ls1 += __shfl_xor_sync(0xffffffffu, ls1, 1);
        ls1 += __shfl_xor_sync(0xffffffffu, ls1, 2);
        const float il0 = 1.f / ls0, il1 = 1.f / ls1;
        #pragma unroll
        for (int j = 2; j < 14; ++j) {
            cf[j][0] *= il0; cf[j][1] *= il0;
            cf[j][2] *= il1; cf[j][3] *= il1;
        }
    }
    __syncthreads();
    const float iv0 = 1.f / (sSum[r0] + sSum[64 + r0]);
    const float iv1 = 1.f / (sSum[r1] + sSum[64 + r1]);
    for (int j = 0; j < jg; ++j) {
        cf[j][0] *= iv0; cf[j][1] *= iv0;
        cf[j][2] *= iv1; cf[j][3] *= iv1;
    }

    float of[8][4];
    #pragma unroll
    for (int nt = 0; nt < 8; ++nt)
        #pragma unroll
        for (int e = 0; e < 4; ++e) of[nt][e] = 0.f;

    const int km = (lane & 7) + ((lane >> 3) & 1) * 8;
    const uint32_t bV = sb + SVH + ((half * 112 + km) * KSTR + (lane >> 4) * 8) * 2;

    #pragma unroll
    for (int kc2 = 0; kc2 < 7; ++kc2) {
        const int j0 = 2 * kc2, j1 = j0 + 1;
        uint32_t ph[4], pl[4];
        ph[0] = packh2(cf[j0][0], cf[j0][1]); pl[0] = packl2h(cf[j0][0], cf[j0][1], ph[0]);
        ph[1] = packh2(cf[j0][2], cf[j0][3]); pl[1] = packl2h(cf[j0][2], cf[j0][3], ph[1]);
        ph[2] = packh2(cf[j1][0], cf[j1][1]); pl[2] = packl2h(cf[j1][0], cf[j1][1], ph[2]);
        ph[3] = packh2(cf[j1][2], cf[j1][3]); pl[3] = packl2h(cf[j1][2], cf[j1][3], ph[3]);
        #pragma unroll
        for (int nd2 = 0; nd2 < 4; ++nd2) {
            uint32_t vh4[4];
            ldsm_x4_t(vh4, bV + (kc2 * 16 * KSTR + nd2 * 16) * 2);
            mma_f16(of[2 * nd2],     ph, vh4 + 0);
            mma_f16(of[2 * nd2],     pl, vh4 + 0);
            mma_f16(of[2 * nd2 + 1], ph, vh4 + 2);
            mma_f16(of[2 * nd2 + 1], pl, vh4 + 2);
        }
    }

    float* sO = (float*)(sm + SO);
    const int rl = lane >> 2, cb = (lane & 3) * 2;
    const int base0 = ((half * 4 + mtile) * 16 + rl) * 64;
    #pragma unroll
    for (int nt = 0; nt < 8; ++nt) {
        sO[base0 + nt * 8 + cb]     = of[nt][0];
        sO[base0 + nt * 8 + cb + 1] = of[nt][1];
        sO[base0 + 8 * 64 + nt * 8 + cb]     = of[nt][2];
        sO[base0 + 8 * 64 + nt * 8 + cb + 1] = of[nt][3];
    }
    __syncthreads();

    const int qi = tid >> 2, cg = (tid & 3) * 16;
    #pragma unroll
    for (int i = 0; i < 4; ++i) {
        const int c = cg + i * 4;
        const float4 a = *(float4*)&sO[qi * 64 + c];
        const float4 bq = *(float4*)&sO[(64 + qi) * 64 + c];
        const float4 o = make_float4(a.x + bq.x, a.y + bq.y, a.z + bq.z, a.w + bq.w);
        uint2 hi, lo;
        hi.x = packh2(o.x, o.y);  lo.x = packl2h(o.x, o.y, hi.x);
        hi.y = packh2(o.z, o.w);  lo.y = packl2h(o.z, o.w, hi.y);
        const size_t off = (baseBT + t0 + qi) * DD + hoff + c;
        *(uint2*)&oh[off] = hi;
        *(uint2*)&ol[off] = lo;
    }
}

// ---------------------------------------------------------------------------
extern "C" void kernel_launch(void* const* d_in, const int* in_sizes, int n_in,
                              void* d_out, int out_size)
{
    const float* x      = (const float*)d_in[0];
    const float* w_qkv  = (const float*)d_in[1];
    const float* w_proj = (const float*)d_in[2];
    const float* b_proj = (const float*)d_in[3];
    float* out = (float*)d_out;

    __half *qkvh, *qkvl, *xh, *xl, *wq, *wp, *ath, *atl;
    cudaGetSymbolAddress((void**)&qkvh, g_qkvh);
    cudaGetSymbolAddress((void**)&qkvl, g_qkvl);
    cudaGetSymbolAddress((void**)&xh,  g_xh);
    cudaGetSymbolAddress((void**)&xl,  g_xl);
    cudaGetSymbolAddress((void**)&wq,  g_wq);
    cudaGetSymbolAddress((void**)&wp,  g_wp);
    cudaGetSymbolAddress((void**)&ath, g_ath);
    cudaGetSymbolAddress((void**)&atl, g_atl);

    const int M = BB * TT;  // 4096

    cudaFuncSetAttribute(gemm_f16x2, cudaFuncAttributeMaxDynamicSharedMemorySize, GEMM_SMEM);
    cudaFuncSetAttribute(attn_mma, cudaFuncAttributeMaxDynamicSharedMemorySize, ATTN_SMEM);

    // 0) convert inputs
    cvt3<<<1184, 256>>>(x, w_qkv, w_proj, xh, xl, wq, wp);

    // 1) qkv = x @ w_qkv — Q columns (<1024) 2-term, K/V columns 1-term
    gemm_f16x2<<<dim3(D3 / 256, M / 128), 512, GEMM_SMEM>>>(
        xh, xl, wq, nullptr, qkvh, qkvl, M, D3, DD, /*n_split=*/DD, nullptr);

    // 2) tensor-core sparse attention (fp16x2; emits fp16 hi/lo)
    attn_mma<<<dim3(TT / 64, HH, BB), 256, ATTN_SMEM>>>(qkvh, qkvl, ath, atl);

    // 3) out = attn @ w_proj + b_proj — 1-term (attn output at fp16)
    gemm_f16x2<<<dim3(DD / 256, M / 128), 512, GEMM_SMEM>>>(
        ath, atl, wp, out, nullptr, nullptr, M, DD, DD, /*n_split=*/0, b_proj);
}

// round 17
// speedup vs baseline: 2.9370x; 1.4069x over previous
#include <cuda_runtime.h>
#include <cuda_bf16.h>
#include <cuda_fp16.h>
#include <cstdint>
#include <cstddef>

// Problem constants
#define BB 2
#define TT 2048
#define DD 1024
#define HH 16
#define HD 64
#define D3 3072

// Scratch (allocation-free rule: __device__ globals)
__device__ __half g_qkv[(size_t)BB * TT * D3];
__device__ __half g_xh[(size_t)BB * TT * DD];
__device__ __half g_wq[(size_t)DD * D3];
__device__ __half g_wp[(size_t)DD * DD];
__device__ __half g_at[(size_t)BB * TT * DD];

// ---------------------------------------------------------------------------
// helpers
// ---------------------------------------------------------------------------
__device__ __forceinline__ uint32_t smem_u32(const void* p) {
    uint32_t a;
    asm("{ .reg .u64 t; cvta.to.shared.u64 t, %1; cvt.u32.u64 %0, t; }"
        : "=r"(a) : "l"(p));
    return a;
}
__device__ __forceinline__ void ldsm_x4(uint32_t* r, uint32_t addr) {
    asm volatile("ldmatrix.sync.aligned.m8n8.x4.shared.b16 {%0,%1,%2,%3}, [%4];"
                 : "=r"(r[0]), "=r"(r[1]), "=r"(r[2]), "=r"(r[3]) : "r"(addr));
}
__device__ __forceinline__ void ldsm_x4_t(uint32_t* r, uint32_t addr) {
    asm volatile("ldmatrix.sync.aligned.m8n8.x4.trans.shared.b16 {%0,%1,%2,%3}, [%4];"
                 : "=r"(r[0]), "=r"(r[1]), "=r"(r[2]), "=r"(r[3]) : "r"(addr));
}
__device__ __forceinline__ void mma_f16(float* d, const uint32_t* a, const uint32_t* b) {
    asm volatile("mma.sync.aligned.m16n8k16.row.col.f32.f16.f16.f32 "
                 "{%0,%1,%2,%3}, {%4,%5,%6,%7}, {%8,%9}, {%0,%1,%2,%3};"
                 : "+f"(d[0]), "+f"(d[1]), "+f"(d[2]), "+f"(d[3])
                 : "r"(a[0]), "r"(a[1]), "r"(a[2]), "r"(a[3]),
                   "r"(b[0]), "r"(b[1]));
}
__device__ __forceinline__ void cp16(uint32_t smem_dst, const void* gsrc) {
    asm volatile("cp.async.cg.shared.global [%0], [%1], 16;"
                 :: "r"(smem_dst), "l"(gsrc));
}
__device__ __forceinline__ void cp16z(uint32_t smem_dst, const void* gsrc, bool valid) {
    const int sz = valid ? 16 : 0;
    asm volatile("cp.async.cg.shared.global [%0], [%1], 16, %2;"
                 :: "r"(smem_dst), "l"(gsrc), "r"(sz));
}
__device__ __forceinline__ void cp_commit() {
    asm volatile("cp.async.commit_group;" ::: "memory");
}
template <int N>
__device__ __forceinline__ void cp_wait() {
    asm volatile("cp.async.wait_group %0;" :: "n"(N) : "memory");
}
__device__ __forceinline__ uint2 cvt4h(const float4 v) {
    __half2 h0 = __floats2half2_rn(v.x, v.y);
    __half2 h1 = __floats2half2_rn(v.z, v.w);
    uint2 r; r.x = *(uint32_t*)&h0; r.y = *(uint32_t*)&h1;
    return r;
}
__device__ __forceinline__ uint32_t packh2(float a, float b) {
    __half2 t = __floats2half2_rn(a, b);
    return *(uint32_t*)&t;
}
__device__ __forceinline__ uint32_t packl2h(float a, float b, uint32_t hi) {
    __half2 h = *(__half2*)&hi;
    __half2 t = __floats2half2_rn(a - __half2float(h.x), b - __half2float(h.y));
    return *(uint32_t*)&t;
}

// ---------------------------------------------------------------------------
// fused conversions: x, w_qkv, w_proj -> fp16
// ---------------------------------------------------------------------------
#define N4_X  ((BB * TT * DD) / 4)
#define N4_WQ ((DD * D3) / 4)
#define N4_WP ((DD * DD) / 4)

__global__ __launch_bounds__(256)
void cvt3(const float* __restrict__ x, const float* __restrict__ wq,
          const float* __restrict__ wp,
          __half* __restrict__ xh, __half* __restrict__ wqo, __half* __restrict__ wpo)
{
    const int stride = gridDim.x * blockDim.x;
    const int t0 = blockIdx.x * blockDim.x + threadIdx.x;
    for (int i = t0; i < N4_X; i += stride)
        ((uint2*)xh)[i] = cvt4h(((const float4*)x)[i]);
    for (int i = t0; i < N4_WQ; i += stride)
        ((uint2*)wqo)[i] = cvt4h(((const float4*)wq)[i]);
    for (int i = t0; i < N4_WP; i += stride)
        ((uint2*)wpo)[i] = cvt4h(((const float4*)wp)[i]);
}

// ---------------------------------------------------------------------------
// fp16 GEMM (single term): C = A*B (+bias). fp32 or fp16 output.
// 128x256 CTA tile, 512 threads, 16 warps of 32x64, 4-stage cp.async ring.
// ---------------------------------------------------------------------------
#define A_STRIDE 40
#define B_STRIDE 264
#define A_BYTES  (128 * A_STRIDE * 2)
#define B_BYTES  (32 * B_STRIDE * 2)
#define OFF_B    A_BYTES
#define STAGE_BYTES (A_BYTES + B_BYTES)           // 27136
#define NSTAGE 4
#define GEMM_SMEM (NSTAGE * STAGE_BYTES)          // 108544

__global__ __launch_bounds__(512, 1)
void gemm_f16(const __half* __restrict__ A, const __half* __restrict__ B,
              float* __restrict__ C, __half* __restrict__ Ch,
              int M, int N, int K,
              const float* __restrict__ bias)
{
    extern __shared__ char sm[];
    const uint32_t sb = smem_u32(sm);
    const int tid = threadIdx.x;
    const int lane = tid & 31, wid = tid >> 5;
    const int wm = wid & 3, wn = wid >> 2;
    const int m0 = blockIdx.y * 128, n0 = blockIdx.x * 256;
    const int NC = K >> 5;

    const int arow = tid >> 2, aseg = tid & 3;
    const int brow = tid >> 5, bseg = tid & 31;

    const __half* gA = A + (size_t)(m0 + arow) * K + aseg * 8;
    const __half* gB = B + (size_t)brow * N + n0 + bseg * 8;
    const uint32_t dA = arow * (A_STRIDE * 2) + aseg * 16;
    const uint32_t dB = brow * (B_STRIDE * 2) + bseg * 16;

    float acc[2][8][4];
    #pragma unroll
    for (int mt = 0; mt < 2; ++mt)
        #pragma unroll
        for (int nt = 0; nt < 8; ++nt)
            #pragma unroll
            for (int q = 0; q < 4; ++q) acc[mt][nt][q] = 0.f;

    auto issue = [&](int cc, int st) {
        const uint32_t stb = sb + (uint32_t)st * STAGE_BYTES;
        cp16(stb + dA, gA + (size_t)cc * 32);
        const size_t kb = (size_t)cc * 32 * N;
        #pragma unroll
        for (int i = 0; i < 2; ++i)
            cp16(stb + OFF_B + dB + i * 16 * (B_STRIDE * 2), gB + kb + (size_t)i * 16 * N);
        cp_commit();
    };

    issue(0, 0);
    if (NC > 1) issue(1, 1);
    if (NC > 2) issue(2, 2);

    const uint32_t aRow = ((wm * 32 + (lane & 15)) * A_STRIDE + (lane >> 4) * 8) * 2;
    const int km = (lane & 7) + ((lane >> 3) & 1) * 8;
    const uint32_t bCol = OFF_B + (km * B_STRIDE + wn * 64 + (lane >> 4) * 8) * 2;

    for (int c = 0; c < NC; ++c) {
        if (c + 2 < NC) cp_wait<2>();
        else if (c + 1 < NC) cp_wait<1>();
        else cp_wait<0>();
        __syncthreads();
        if (c + 3 < NC) issue(c + 3, (c + 3) & 3);

        const uint32_t stb = sb + (uint32_t)(c & 3) * STAGE_BYTES;
        #pragma unroll
        for (int ks = 0; ks < 2; ++ks) {
            const int k0 = ks * 16;
            uint32_t ar[2][4];
            #pragma unroll
            for (int mt = 0; mt < 2; ++mt)
                ldsm_x4(ar[mt], stb + aRow + (mt * 16 * A_STRIDE + k0) * 2);
            #pragma unroll
            for (int j = 0; j < 4; ++j) {
                uint32_t b4[4];
                ldsm_x4_t(b4, stb + bCol + (k0 * B_STRIDE + j * 16) * 2);
                #pragma unroll
                for (int mt = 0; mt < 2; ++mt)
                    #pragma unroll
                    for (int u = 0; u < 2; ++u)
                        mma_f16(acc[mt][j * 2 + u], ar[mt], b4 + u * 2);
            }
        }
    }

    const int row = m0 + wm * 32 + (lane >> 2);
    const int colb = n0 + wn * 64 + (lane & 3) * 2;
    #pragma unroll
    for (int nt = 0; nt < 8; ++nt) {
        float2 bv = make_float2(0.f, 0.f);
        if (bias) bv = *(const float2*)(bias + colb + nt * 8);
        #pragma unroll
        for (int mt = 0; mt < 2; ++mt) {
            const float* d = acc[mt][nt];
            const float v00 = d[0] + bv.x, v01 = d[1] + bv.y;
            const float v10 = d[2] + bv.x, v11 = d[3] + bv.y;
            const size_t i0 = (size_t)(row + mt * 16) * N + colb + nt * 8;
            const size_t i1 = (size_t)(row + mt * 16 + 8) * N + colb + nt * 8;
            if (Ch) {
                *(uint32_t*)&Ch[i0] = packh2(v00, v01);
                *(uint32_t*)&Ch[i1] = packh2(v10, v11);
            } else {
                *(float2*)&C[i0] = make_float2(v00, v01);
                *(float2*)&C[i1] = make_float2(v10, v11);
            }
        }
    }
}

// ---------------------------------------------------------------------------
// Tensor-core sparse attention, full fp16 except P (hi/lo).
// Q/K/V single fp16; QK^T = 1 MMA per frag; PV = Ph*V + Pl*V.
// smem ~73 KB; sO reuses dead Q+K region (41472 B >= 32768 B).
// ---------------------------------------------------------------------------
#define KSTR 72
#define SQH 0
#define SKH (64 * KSTR * 2)                 // 9216
#define SVH (SKH + 224 * KSTR * 2)          // 41472
#define SRED (SVH + 224 * KSTR * 2)         // 73728
#define SO  0
#define ATTN_SMEM (SRED + 1024)             // 74752

__global__ __launch_bounds__(256, 2)
void attn_mma(const __half* __restrict__ qkv,
              __half* __restrict__ oh)
{
    const int t0 = blockIdx.x * 64;
    const int h  = blockIdx.y;
    const int b  = blockIdx.z;
    const int tid = threadIdx.x;
    const int lane = tid & 31, wid = tid >> 5;
    const int mtile = wid & 3, half = wid >> 2;

    extern __shared__ char sm[];
    const uint32_t sb = smem_u32(sm);
    const size_t baseBT = (size_t)b * TT;
    const int hoff = h * HD;

    // ---- group A: stage Q + K ----
    for (int idx = tid; idx < 64 * 8; idx += 256) {
        const int r = idx >> 3, c = (idx & 7) * 8;
        cp16(sb + SQH + (r * KSTR + c) * 2,
             qkv + (baseBT + t0 + r) * D3 + hoff + c);
    }
    for (int idx = tid; idx < 224 * 8; idx += 256) {
        const int r = idx >> 3, c = (idx & 7) * 8;
        int t = 0; bool valid = false;
        if (r < 128)      { t = r * 16;              valid = true; }
        else if (r < 207) { t = t0 - 15 + (r - 128); valid = (t >= 0); }
        if (t < 0) t = 0;
        cp16z(sb + SKH + (r * KSTR + c) * 2,
              qkv + (baseBT + t) * D3 + hoff + c + 1024, valid);
    }
    cp_commit();
    // ---- group B: stage V (completes during S-phase) ----
    for (int idx = tid; idx < 224 * 8; idx += 256) {
        const int r = idx >> 3, c = (idx & 7) * 8;
        int t = 0; bool valid = false;
        if (r < 128)      { t = r * 16;              valid = true; }
        else if (r < 207) { t = t0 - 15 + (r - 128); valid = (t >= 0); }
        if (t < 0) t = 0;
        cp16z(sb + SVH + (r * KSTR + c) * 2,
              qkv + (baseBT + t) * D3 + hoff + c + 2048, valid);
    }
    cp_commit();
    cp_wait<1>();
    __syncthreads();

    uint32_t qh[4][4];
    const uint32_t aQ = sb + SQH + ((mtile * 16 + (lane & 15)) * KSTR + (lane >> 4) * 8) * 2;
    #pragma unroll
    for (int kc = 0; kc < 4; ++kc)
        ldsm_x4(qh[kc], aQ + kc * 32);

    const uint32_t bK = sb + SKH +
        ((half * 112 + (lane & 7) + ((lane >> 4) & 1) * 8) * KSTR + ((lane >> 3) & 1) * 8) * 2;

    float cf[14][4];
    #pragma unroll
    for (int j = 0; j < 14; ++j)
        #pragma unroll
        for (int e = 0; e < 4; ++e) cf[j][e] = 0.f;

    #pragma unroll
    for (int jj = 0; jj < 7; ++jj) {
        #pragma unroll
        for (int kc = 0; kc < 4; ++kc) {
            uint32_t kh4[4];
            ldsm_x4(kh4, bK + (jj * 16 * KSTR + kc * 16) * 2);
            mma_f16(cf[2 * jj],     qh[kc], kh4 + 0);
            mma_f16(cf[2 * jj + 1], qh[kc], kh4 + 2);
        }
    }
    #pragma unroll
    for (int j = 0; j < 14; ++j)
        #pragma unroll
        for (int e = 0; e < 4; ++e) cf[j][e] *= 0.125f;

    const int r0 = mtile * 16 + (lane >> 2);
    const int r1 = r0 + 8;
    float* sMax = (float*)(sm + SRED);
    float* sSum = (float*)(sm + SRED + 512);
    const int jg = (half == 0) ? 14 : 2;

    float gm0 = -1e30f, gm1 = -1e30f;
    for (int j = 0; j < jg; ++j) {
        gm0 = fmaxf(gm0, fmaxf(cf[j][0], cf[j][1]));
        gm1 = fmaxf(gm1, fmaxf(cf[j][2], cf[j][3]));
    }
    gm0 = fmaxf(gm0, __shfl_xor_sync(0xffffffffu, gm0, 1));
    gm0 = fmaxf(gm0, __shfl_xor_sync(0xffffffffu, gm0, 2));
    gm1 = fmaxf(gm1, __shfl_xor_sync(0xffffffffu, gm1, 1));
    gm1 = fmaxf(gm1, __shfl_xor_sync(0xffffffffu, gm1, 2));
    if ((lane & 3) == 0) { sMax[half * 64 + r0] = gm0; sMax[half * 64 + r1] = gm1; }
    cp_wait<0>();
    __syncthreads();
    const float M0 = fmaxf(sMax[r0], sMax[64 + r0]);
    const float M1 = fmaxf(sMax[r1], sMax[64 + r1]);

    float gs0 = 0.f, gs1 = 0.f;
    for (int j = 0; j < jg; ++j) {
        cf[j][0] = __expf(cf[j][0] - M0); cf[j][1] = __expf(cf[j][1] - M0);
        cf[j][2] = __expf(cf[j][2] - M1); cf[j][3] = __expf(cf[j][3] - M1);
        gs0 += cf[j][0] + cf[j][1];
        gs1 += cf[j][2] + cf[j][3];
    }
    gs0 += __shfl_xor_sync(0xffffffffu, gs0, 1);
    gs0 += __shfl_xor_sync(0xffffffffu, gs0, 2);
    gs1 += __shfl_xor_sync(0xffffffffu, gs1, 1);
    gs1 += __shfl_xor_sync(0xffffffffu, gs1, 2);
    if ((lane & 3) == 0) { sSum[half * 64 + r0] = gs0; sSum[half * 64 + r1] = gs1; }

    if (half == 1) {
        float lm0 = -1e30f, lm1 = -1e30f;
        #pragma unroll
        for (int j = 2; j < 14; ++j) {
            const int c0 = (14 + j) * 8 + (lane & 3) * 2 - 128;
            const int c1 = c0 + 1;
            if ((unsigned)(c0 - r0) > 15u) cf[j][0] = -1e30f;
            if ((unsigned)(c1 - r0) > 15u) cf[j][1] = -1e30f;
            if ((unsigned)(c0 - r1) > 15u) cf[j][2] = -1e30f;
            if ((unsigned)(c1 - r1) > 15u) cf[j][3] = -1e30f;
            lm0 = fmaxf(lm0, fmaxf(cf[j][0], cf[j][1]));
            lm1 = fmaxf(lm1, fmaxf(cf[j][2], cf[j][3]));
        }
        lm0 = fmaxf(lm0, __shfl_xor_sync(0xffffffffu, lm0, 1));
        lm0 = fmaxf(lm0, __shfl_xor_sync(0xffffffffu, lm0, 2));
        lm1 = fmaxf(lm1, __shfl_xor_sync(0xffffffffu, lm1, 1));
        lm1 = fmaxf(lm1, __shfl_xor_sync(0xffffffffu, lm1, 2));
        float ls0 = 0.f, ls1 = 0.f;
        #pragma unroll
        for (int j = 2; j < 14; ++j) {
            cf[j][0] = __expf(cf[j][0] - lm0); cf[j][1] = __expf(cf[j][1] - lm0);
            cf[j][2] = __expf(cf[j][2] - lm1); cf[j][3] = __expf(cf[j][3] - lm1);
            ls0 += cf[j][0] + cf[j][1];
            ls1 += cf[j][2] + cf[j][3];
        }
        ls0 += __shfl_xor_sync(0xffffffffu, ls0, 1);
        ls0 += __shfl_xor_sync(0xffffffffu, ls0, 2);
        ls1 += __shfl_xor_sync(0xffffffffu, ls1, 1);
        ls1 += __shfl_xor_sync(0xffffffffu, ls1, 2);
        const float il0 = 1.f / ls0, il1 = 1.f / ls1;
        #pragma unroll
        for (int j = 2; j < 14; ++j) {
            cf[j][0] *= il0; cf[j][1] *= il0;
            cf[j][2] *= il1; cf[j][3] *= il1;
        }
    }
    __syncthreads();
    const float iv0 = 1.f / (sSum[r0] + sSum[64 + r0]);
    const float iv1 = 1.f / (sSum[r1] + sSum[64 + r1]);
    for (int j = 0; j < jg; ++j) {
        cf[j][0] *= iv0; cf[j][1] *= iv0;
        cf[j][2] *= iv1; cf[j][3] *= iv1;
    }

    float of[8][4];
    #pragma unroll
    for (int nt = 0; nt < 8; ++nt)
        #pragma unroll
        for (int e = 0; e < 4; ++e) of[nt][e] = 0.f;

    const int km = (lane & 7) + ((lane >> 3) & 1) * 8;
    const uint32_t bV = sb + SVH + ((half * 112 + km) * KSTR + (lane >> 4) * 8) * 2;

    #pragma unroll
    for (int kc2 = 0; kc2 < 7; ++kc2) {
        const int j0 = 2 * kc2, j1 = j0 + 1;
        uint32_t ph[4], pl[4];
        ph[0] = packh2(cf[j0][0], cf[j0][1]); pl[0] = packl2h(cf[j0][0], cf[j0][1], ph[0]);
        ph[1] = packh2(cf[j0][2], cf[j0][3]); pl[1] = packl2h(cf[j0][2], cf[j0][3], ph[1]);
        ph[2] = packh2(cf[j1][0], cf[j1][1]); pl[2] = packl2h(cf[j1][0], cf[j1][1], ph[2]);
        ph[3] = packh2(cf[j1][2], cf[j1][3]); pl[3] = packl2h(cf[j1][2], cf[j1][3], ph[3]);
        #pragma unroll
        for (int nd2 = 0; nd2 < 4; ++nd2) {
            uint32_t vh4[4];
            ldsm_x4_t(vh4, bV + (kc2 * 16 * KSTR + nd2 * 16) * 2);
            mma_f16(of[2 * nd2],     ph, vh4 + 0);
            mma_f16(of[2 * nd2],     pl, vh4 + 0);
            mma_f16(of[2 * nd2 + 1], ph, vh4 + 2);
            mma_f16(of[2 * nd2 + 1], pl, vh4 + 2);
        }
    }

    float* sO = (float*)(sm + SO);
    const int rl = lane >> 2, cb = (lane & 3) * 2;
    const int base0 = ((half * 4 + mtile) * 16 + rl) * 64;
    #pragma unroll
    for (int nt = 0; nt < 8; ++nt) {
        sO[base0 + nt * 8 + cb]     = of[nt][0];
        sO[base0 + nt * 8 + cb + 1] = of[nt][1];
        sO[base0 + 8 * 64 + nt * 8 + cb]     = of[nt][2];
        sO[base0 + 8 * 64 + nt * 8 + cb + 1] = of[nt][3];
    }
    __syncthreads();

    const int qi = tid >> 2, cg = (tid & 3) * 16;
    #pragma unroll
    for (int i = 0; i < 4; ++i) {
        const int c = cg + i * 4;
        const float4 a = *(float4*)&sO[qi * 64 + c];
        const float4 bq = *(float4*)&sO[(64 + qi) * 64 + c];
        uint2 hi;
        hi.x = packh2(a.x + bq.x, a.y + bq.y);
        hi.y = packh2(a.z + bq.z, a.w + bq.w);
        *(uint2*)&oh[(baseBT + t0 + qi) * DD + hoff + c] = hi;
    }
}

// ---------------------------------------------------------------------------
extern "C" void kernel_launch(void* const* d_in, const int* in_sizes, int n_in,
                              void* d_out, int out_size)
{
    const float* x      = (const float*)d_in[0];
    const float* w_qkv  = (const float*)d_in[1];
    const float* w_proj = (const float*)d_in[2];
    const float* b_proj = (const float*)d_in[3];
    float* out = (float*)d_out;

    __half *qkv, *xh, *wq, *wp, *at;
    cudaGetSymbolAddress((void**)&qkv, g_qkv);
    cudaGetSymbolAddress((void**)&xh,  g_xh);
    cudaGetSymbolAddress((void**)&wq,  g_wq);
    cudaGetSymbolAddress((void**)&wp,  g_wp);
    cudaGetSymbolAddress((void**)&at,  g_at);

    const int M = BB * TT;  // 4096

    cudaFuncSetAttribute(gemm_f16, cudaFuncAttributeMaxDynamicSharedMemorySize, GEMM_SMEM);
    cudaFuncSetAttribute(attn_mma, cudaFuncAttributeMaxDynamicSharedMemorySize, ATTN_SMEM);

    // 0) convert inputs to fp16
    cvt3<<<1184, 256>>>(x, w_qkv, w_proj, xh, wq, wp);

    // 1) qkv = x @ w_qkv  (fp16 out)
    gemm_f16<<<dim3(D3 / 256, M / 128), 512, GEMM_SMEM>>>(
        xh, wq, nullptr, qkv, M, D3, DD, nullptr);

    // 2) tensor-core sparse attention (fp16; P kept hi/lo internally)
    attn_mma<<<dim3(TT / 64, HH, BB), 256, ATTN_SMEM>>>(qkv, at);

    // 3) out = attn @ w_proj + b_proj (fp32 out)
    gemm_f16<<<dim3(DD / 256, M / 128), 512, GEMM_SMEM>>>(
        at, wp, out, nullptr, M, DD, DD, b_proj);
}